// round 2
// baseline (speedup 1.0000x reference)
#include <cuda_runtime.h>
#include <cstdint>

#define BT   65536
#define T_   2048
#define B_   32
#define H_   768
#define G4   3072

typedef unsigned long long ull;

// ---------------- scratch (static device memory; no allocs) ----------------
__device__ float g_m1[(size_t)BT * 256];
__device__ float g_m2[(size_t)BT * 256];
__device__ float g_xg[(size_t)BT * G4];     // [b*T+t][4H]
__device__ float g_hs[(size_t)BT * H_];     // [b*T+t][H]
__device__ float g_h[2][H_ * B_];           // double-buffered h, layout [j][b]
__device__ float g_bias[G4];
__device__ unsigned g_bar;

// ---------------- f32x2 helpers ----------------
__device__ __forceinline__ ull pk2(float lo, float hi) {
    ull r; asm("mov.b64 %0,{%1,%2};" : "=l"(r) : "f"(lo), "f"(hi)); return r;
}
__device__ __forceinline__ void fma2(ull& d, ull a, ull b) {
    asm("fma.rn.f32x2 %0,%1,%2,%0;" : "+l"(d) : "l"(a), "l"(b));
}
__device__ __forceinline__ float2 upk2(ull v) {
    float lo, hi; asm("mov.b64 {%0,%1},%2;" : "=f"(lo), "=f"(hi) : "l"(v));
    float2 r; r.x = lo; r.y = hi; return r;
}

__device__ __forceinline__ float sigf(float x) {
    return __fdividef(1.f, 1.f + __expf(-x));
}
__device__ __forceinline__ float tanh_(float x) {
    return 2.f * sigf(2.f * x) - 1.f;
}

// ---------------- tiny kernels ----------------
__global__ void bias_kernel(const float* __restrict__ bi, const float* __restrict__ bh) {
    int i = blockIdx.x * 256 + threadIdx.x;
    if (i < G4) g_bias[i] = bi[i] + bh[i];
}
__global__ void zero_bar_kernel() { g_bar = 0u; }

// ---------------- generic SGEMM: C[M,N] = concatA[M,K] @ W[K,N] (+bias)(+relu) --------
// A cols [0,split) from A1 (lda1), [split,K) from A2 (lda2).
// Tiles: 128x128x16, 256 threads, 8x8 micro-tile via f32x2.
// Requires M%128==0, N%128==0, K%16==0, split%16==0.
__global__ __launch_bounds__(256, 2)
void sgemm_kernel(const float* __restrict__ A1, int lda1,
                  const float* __restrict__ A2, int lda2, int split,
                  const float* __restrict__ W,
                  const float* __restrict__ bias, int relu,
                  float* __restrict__ C, int N, int K)
{
    __shared__ float As[16][128];
    __shared__ float Bs[16][128];
    const int tid = threadIdx.x;
    const int tx = tid & 15, ty = tid >> 4;
    const int bm = blockIdx.y << 7, bn = blockIdx.x << 7;

    ull acc[8][4];
#pragma unroll
    for (int i = 0; i < 8; i++)
#pragma unroll
        for (int j = 0; j < 4; j++) acc[i][j] = 0ull;

    const int aq0 = tid, aq1 = tid + 256;
    const int ar0 = aq0 >> 2, ak0 = (aq0 & 3) << 2;
    const int ar1 = aq1 >> 2, ak1 = (aq1 & 3) << 2;
    const int bkk = tid >> 5, bcc = (tid & 31) << 2;

    float4 pa0, pa1, pb0, pb1;

    auto ldTiles = [&](int k0) {
        int kg0 = k0 + ak0;
        pa0 = (kg0 < split)
            ? *(const float4*)(A1 + (size_t)(bm + ar0) * lda1 + kg0)
            : *(const float4*)(A2 + (size_t)(bm + ar0) * lda2 + (kg0 - split));
        int kg1 = k0 + ak1;
        pa1 = (kg1 < split)
            ? *(const float4*)(A1 + (size_t)(bm + ar1) * lda1 + kg1)
            : *(const float4*)(A2 + (size_t)(bm + ar1) * lda2 + (kg1 - split));
        pb0 = *(const float4*)(W + (size_t)(k0 + bkk) * N + bn + bcc);
        pb1 = *(const float4*)(W + (size_t)(k0 + bkk + 8) * N + bn + bcc);
    };
    auto stTiles = [&]() {
        As[ak0 + 0][ar0] = pa0.x; As[ak0 + 1][ar0] = pa0.y;
        As[ak0 + 2][ar0] = pa0.z; As[ak0 + 3][ar0] = pa0.w;
        As[ak1 + 0][ar1] = pa1.x; As[ak1 + 1][ar1] = pa1.y;
        As[ak1 + 2][ar1] = pa1.z; As[ak1 + 3][ar1] = pa1.w;
        *(float4*)&Bs[bkk][bcc] = pb0;
        *(float4*)&Bs[bkk + 8][bcc] = pb1;
    };
    auto comp = [&]() {
#pragma unroll
        for (int kk = 0; kk < 16; kk++) {
            float4 a0 = *(const float4*)&As[kk][ty << 3];
            float4 a1 = *(const float4*)&As[kk][(ty << 3) + 4];
            ulonglong2 b01 = *(const ulonglong2*)&Bs[kk][tx << 3];
            ulonglong2 b23 = *(const ulonglong2*)&Bs[kk][(tx << 3) + 4];
            float ar[8] = {a0.x, a0.y, a0.z, a0.w, a1.x, a1.y, a1.z, a1.w};
#pragma unroll
            for (int i = 0; i < 8; i++) {
                ull av = pk2(ar[i], ar[i]);
                fma2(acc[i][0], av, b01.x);
                fma2(acc[i][1], av, b01.y);
                fma2(acc[i][2], av, b23.x);
                fma2(acc[i][3], av, b23.y);
            }
        }
    };

    ldTiles(0);
    stTiles();
    __syncthreads();
    for (int k0 = 0; k0 < K; k0 += 16) {
        bool more = (k0 + 16) < K;
        if (more) ldTiles(k0 + 16);
        comp();
        __syncthreads();
        if (more) { stTiles(); __syncthreads(); }
    }

#pragma unroll
    for (int i = 0; i < 8; i++) {
        int row = bm + (ty << 3) + i;
        float* cp = C + (size_t)row * N + bn + (tx << 3);
#pragma unroll
        for (int j = 0; j < 4; j++) {
            float2 v = upk2(acc[i][j]);
            if (bias) {
                int col = bn + (tx << 3) + 2 * j;
                v.x += bias[col]; v.y += bias[col + 1];
            }
            if (relu) { v.x = fmaxf(v.x, 0.f); v.y = fmaxf(v.y, 0.f); }
            *(float2*)(cp + 2 * j) = v;
        }
    }
}

// ---------------- grid barrier ----------------
__device__ __forceinline__ void gridbar(unsigned target) {
    __threadfence();
    __syncthreads();
    if (threadIdx.x == 0) {
        atomicAdd(&g_bar, 1u);
        unsigned v;
        for (;;) {
            asm volatile("ld.acquire.gpu.u32 %0, [%1];" : "=r"(v) : "l"(&g_bar) : "memory");
            if (v >= target) break;
            __nanosleep(64);
        }
    }
    __syncthreads();
}

// ---------------- persistent LSTM scan ----------------
// 128 blocks x 256 threads. Block k owns hidden units [6k, 6k+6).
// SMEM: w_s[768*24] (its 24 w_hh columns, order c=q*6+u -> col q*768+j0+u),
//       red (8 warps x 32 b x 13 ull partial pairs), c_s[6*32].
#define SMEM_SCAN_FLOATS (18432 + 6656 + 192)
__global__ __launch_bounds__(256)
void scan_kernel(const float* __restrict__ w_hh)
{
    extern __shared__ float sm[];
    float* w_s   = sm;                 // 18432 floats
    float* red_f = sm + 18432;         // 6656 floats (= 8*32*13 ull)
    ull*   red_u = (ull*)red_f;
    float* c_s   = red_f + 6656;       // 192 floats

    const int tid = threadIdx.x, lane = tid & 31, warp = tid >> 5;
    const int j0 = blockIdx.x * 6;

    // load weight slice (persists all 2048 steps)
    for (int idx = tid; idx < 768 * 24; idx += 256) {
        int k = idx / 24, c = idx - k * 24;
        int q = c / 6, u = c - q * 6;
        w_s[idx] = w_hh[(size_t)k * G4 + q * H_ + j0 + u];
    }
    if (tid < 192) {
        c_s[tid] = 0.f;
        int u = tid >> 5, b = tid & 31;
        g_h[0][(j0 + u) * 32 + b] = 0.f;
    }
    gridbar(128u);  // weights loaded, h0 zeroed everywhere

    for (int t = 0; t < T_; t++) {
        const float* hcur = g_h[t & 1];
        float*       hnxt = g_h[(t + 1) & 1];

        // prefetch input-gate preactivations (DRAM latency hides under GEMM)
        float xgv[4];
        if (tid < 192) {
            int u = tid >> 5, b = tid & 31;
            const float* xp = g_xg + (size_t)(b * T_ + t) * G4 + j0 + u;
            xgv[0] = xp[0];
            xgv[1] = xp[H_];
            xgv[2] = xp[2 * H_];
            xgv[3] = xp[3 * H_];
        }

        // split-K GEMM: warp covers k in [warp*96, warp*96+96), lane = batch b
        ull acc[12];
#pragma unroll
        for (int j = 0; j < 12; j++) acc[j] = 0ull;

        const float* hp  = hcur + warp * 96 * 32 + lane;
        const float* wsp = w_s + warp * 96 * 24;
        float ha[8];
#pragma unroll
        for (int i = 0; i < 8; i++) ha[i] = hp[i * 32];

#pragma unroll 2
        for (int kc = 0; kc < 96; kc += 8) {
            float hb[8];
            bool more = (kc + 8) < 96;
            if (more) {
#pragma unroll
                for (int i = 0; i < 8; i++) hb[i] = hp[(kc + 8 + i) * 32];
            }
#pragma unroll
            for (int i = 0; i < 8; i++) {
                ull hv = pk2(ha[i], ha[i]);
                const ulonglong2* wv = (const ulonglong2*)(wsp + (kc + i) * 24);
                ulonglong2 w0 = wv[0], w1 = wv[1], w2 = wv[2];
                ulonglong2 w3 = wv[3], w4 = wv[4], w5 = wv[5];
                fma2(acc[0],  hv, w0.x); fma2(acc[1],  hv, w0.y);
                fma2(acc[2],  hv, w1.x); fma2(acc[3],  hv, w1.y);
                fma2(acc[4],  hv, w2.x); fma2(acc[5],  hv, w2.y);
                fma2(acc[6],  hv, w3.x); fma2(acc[7],  hv, w3.y);
                fma2(acc[8],  hv, w4.x); fma2(acc[9],  hv, w4.y);
                fma2(acc[10], hv, w5.x); fma2(acc[11], hv, w5.y);
            }
            if (more) {
#pragma unroll
                for (int i = 0; i < 8; i++) ha[i] = hb[i];
            }
        }

        // write split-K partials
        ull* rp = red_u + (size_t)tid * 13;
#pragma unroll
        for (int j = 0; j < 12; j++) rp[j] = acc[j];
        __syncthreads();

        // gate phase: thread (u,b) -> one hidden unit, one batch
        if (tid < 192) {
            int u = tid >> 5, b = tid & 31;
            float pre[4];
#pragma unroll
            for (int q = 0; q < 4; q++) {
                int c = q * 6 + u, p = c >> 1, hs = c & 1;
                float s = xgv[q];
#pragma unroll
                for (int w = 0; w < 8; w++)
                    s += red_f[(((w * 32 + b) * 13 + p) << 1) + hs];
                pre[q] = s;
            }
            float ig = sigf(pre[0]);
            float fg = sigf(pre[1]);
            float gg = tanh_(pre[2]);
            float og = sigf(pre[3]);
            float cn = fg * c_s[u * 32 + b] + ig * gg;
            c_s[u * 32 + b] = cn;
            float hn = og * tanh_(cn);
            hnxt[(j0 + u) * 32 + b] = hn;
            g_hs[(size_t)(b * T_ + t) * H_ + j0 + u] = hn;
        }
        gridbar((unsigned)(t + 2) * 128u);
    }
}

// ---------------- host launcher ----------------
extern "C" void kernel_launch(void* const* d_in, const int* in_sizes, int n_in,
                              void* d_out, int out_size)
{
    const float* x      = (const float*)d_in[0];
    const float* mels   = (const float*)d_in[1];
    const float* w1     = (const float*)d_in[2];
    const float* b1     = (const float*)d_in[3];
    const float* w2     = (const float*)d_in[4];
    const float* b2     = (const float*)d_in[5];
    const float* w_ih   = (const float*)d_in[6];
    const float* w_hh   = (const float*)d_in[7];
    const float* b_ih   = (const float*)d_in[8];
    const float* b_hh   = (const float*)d_in[9];
    const float* w_proj = (const float*)d_in[10];
    float* out = (float*)d_out;

    float *p_m1, *p_m2, *p_xg, *p_hs, *p_bias;
    cudaGetSymbolAddress((void**)&p_m1,  g_m1);
    cudaGetSymbolAddress((void**)&p_m2,  g_m2);
    cudaGetSymbolAddress((void**)&p_xg,  g_xg);
    cudaGetSymbolAddress((void**)&p_hs,  g_hs);
    cudaGetSymbolAddress((void**)&p_bias, g_bias);

    cudaFuncSetAttribute(scan_kernel, cudaFuncAttributeMaxDynamicSharedMemorySize,
                         SMEM_SCAN_FLOATS * 4);

    // fused LSTM bias
    bias_kernel<<<12, 256>>>(b_ih, b_hh);

    // PreNet layer 1: [65536,128] @ [128,256] + b1, relu
    sgemm_kernel<<<dim3(2, 512), 256>>>(mels, 128, mels, 128, 128,
                                        w1, b1, 1, p_m1, 256, 128);
    // PreNet layer 2: [65536,256] @ [256,256] + b2, relu
    sgemm_kernel<<<dim3(2, 512), 256>>>(p_m1, 256, p_m1, 256, 256,
                                        w2, b2, 1, p_m2, 256, 256);
    // xg = concat(x, m2) @ w_ih + (b_ih+b_hh)   [65536,768]x[768,3072]
    sgemm_kernel<<<dim3(24, 512), 256>>>(x, 512, p_m2, 256, 512,
                                         w_ih, p_bias, 0, p_xg, 3072, 768);

    // LSTM recurrence (persistent cooperative kernel)
    zero_bar_kernel<<<1, 1>>>();
    scan_kernel<<<128, 256, SMEM_SCAN_FLOATS * 4>>>(w_hh);

    // projection: [65536,768] @ [768,128]
    sgemm_kernel<<<dim3(1, 512), 256>>>(p_hs, 768, p_hs, 768, 768,
                                        w_proj, nullptr, 0, out, 128, 768);
}

// round 3
// speedup vs baseline: 1.0486x; 1.0486x over previous
#include <cuda_runtime.h>
#include <cstdint>

#define BT   65536
#define T_   2048
#define B_   32
#define H_   768
#define G4   3072

typedef unsigned long long ull;

// ---------------- scratch (static device memory; no allocs) ----------------
__device__ float g_m1[(size_t)BT * 256];
__device__ float g_m2[(size_t)BT * 256];
__device__ float g_xg[(size_t)BT * G4];     // [b*T+t][4H]
__device__ float g_hs[(size_t)BT * H_];     // [b*T+t][H]
__device__ float g_h[2][H_ * B_];           // double-buffered h, layout [j][b]
__device__ float g_bias[G4];
__device__ unsigned g_flag[128 * 32];       // per-block flags, 128B stride

// ---------------- f32x2 helpers ----------------
__device__ __forceinline__ ull pk2(float lo, float hi) {
    ull r; asm("mov.b64 %0,{%1,%2};" : "=l"(r) : "f"(lo), "f"(hi)); return r;
}
__device__ __forceinline__ void fma2(ull& d, ull a, ull b) {
    asm("fma.rn.f32x2 %0,%1,%2,%0;" : "+l"(d) : "l"(a), "l"(b));
}
__device__ __forceinline__ float2 upk2(ull v) {
    float lo, hi; asm("mov.b64 {%0,%1},%2;" : "=f"(lo), "=f"(hi) : "l"(v));
    float2 r; r.x = lo; r.y = hi; return r;
}

__device__ __forceinline__ float sigf(float x) {
    return __fdividef(1.f, 1.f + __expf(-x));
}
__device__ __forceinline__ float tanh_(float x) {
    return 2.f * sigf(2.f * x) - 1.f;
}

// ---------------- init: fused bias + flag reset ----------------
__global__ void init_kernel(const float* __restrict__ bi, const float* __restrict__ bh) {
    int i = blockIdx.x * 256 + threadIdx.x;
    if (i < 128 * 32) g_flag[i] = 0u;
    if (i < G4) g_bias[i] = bi[i] + bh[i];
}

// ---------------- generic SGEMM: C[M,N] = concatA[M,K] @ W[K,N] (+bias)(+relu) --------
// A cols [0,split) from A1 (lda1), [split,K) from A2 (lda2).
// Tiles: 128x128x16, 256 threads, 8x8 micro-tile via f32x2.
// As padded to 132 (store conflicts 4->2 way); Bs swizzled c->c+4*(c>>5) (reads conflict-free).
__device__ __forceinline__ int swz(int c) { return c + ((c >> 5) << 2); }

__global__ __launch_bounds__(256, 2)
void sgemm_kernel(const float* __restrict__ A1, int lda1,
                  const float* __restrict__ A2, int lda2, int split,
                  const float* __restrict__ W,
                  const float* __restrict__ bias, int relu,
                  float* __restrict__ C, int N, int K)
{
    __shared__ float As[16][132];
    __shared__ float Bs[16][144];
    const int tid = threadIdx.x;
    const int tx = tid & 15, ty = tid >> 4;
    const int bm = blockIdx.y << 7, bn = blockIdx.x << 7;

    ull acc[8][4];
#pragma unroll
    for (int i = 0; i < 8; i++)
#pragma unroll
        for (int j = 0; j < 4; j++) acc[i][j] = 0ull;

    const int aq0 = tid, aq1 = tid + 256;
    const int ar0 = aq0 >> 2, ak0 = (aq0 & 3) << 2;
    const int ar1 = aq1 >> 2, ak1 = (aq1 & 3) << 2;
    const int bkk = tid >> 5, bcc = (tid & 31) << 2;

    float4 pa0, pa1, pb0, pb1;

    auto ldTiles = [&](int k0) {
        int kg0 = k0 + ak0;
        pa0 = (kg0 < split)
            ? *(const float4*)(A1 + (size_t)(bm + ar0) * lda1 + kg0)
            : *(const float4*)(A2 + (size_t)(bm + ar0) * lda2 + (kg0 - split));
        int kg1 = k0 + ak1;
        pa1 = (kg1 < split)
            ? *(const float4*)(A1 + (size_t)(bm + ar1) * lda1 + kg1)
            : *(const float4*)(A2 + (size_t)(bm + ar1) * lda2 + (kg1 - split));
        pb0 = *(const float4*)(W + (size_t)(k0 + bkk) * N + bn + bcc);
        pb1 = *(const float4*)(W + (size_t)(k0 + bkk + 8) * N + bn + bcc);
    };
    auto stTiles = [&]() {
        As[ak0 + 0][ar0] = pa0.x; As[ak0 + 1][ar0] = pa0.y;
        As[ak0 + 2][ar0] = pa0.z; As[ak0 + 3][ar0] = pa0.w;
        As[ak1 + 0][ar1] = pa1.x; As[ak1 + 1][ar1] = pa1.y;
        As[ak1 + 2][ar1] = pa1.z; As[ak1 + 3][ar1] = pa1.w;
        *(float4*)&Bs[bkk][swz(bcc)] = pb0;
        *(float4*)&Bs[bkk + 8][swz(bcc)] = pb1;
    };
    auto comp = [&]() {
#pragma unroll
        for (int kk = 0; kk < 16; kk++) {
            float4 a0 = *(const float4*)&As[kk][ty << 3];
            float4 a1 = *(const float4*)&As[kk][(ty << 3) + 4];
            ulonglong2 b01 = *(const ulonglong2*)&Bs[kk][swz(tx << 3)];
            ulonglong2 b23 = *(const ulonglong2*)&Bs[kk][swz((tx << 3) + 4)];
            float ar[8] = {a0.x, a0.y, a0.z, a0.w, a1.x, a1.y, a1.z, a1.w};
#pragma unroll
            for (int i = 0; i < 8; i++) {
                ull av = pk2(ar[i], ar[i]);
                fma2(acc[i][0], av, b01.x);
                fma2(acc[i][1], av, b01.y);
                fma2(acc[i][2], av, b23.x);
                fma2(acc[i][3], av, b23.y);
            }
        }
    };

    ldTiles(0);
    stTiles();
    __syncthreads();
    for (int k0 = 0; k0 < K; k0 += 16) {
        bool more = (k0 + 16) < K;
        if (more) ldTiles(k0 + 16);
        comp();
        __syncthreads();
        if (more) { stTiles(); __syncthreads(); }
    }

#pragma unroll
    for (int i = 0; i < 8; i++) {
        int row = bm + (ty << 3) + i;
        float* cp = C + (size_t)row * N + bn + (tx << 3);
#pragma unroll
        for (int j = 0; j < 4; j++) {
            float2 v = upk2(acc[i][j]);
            if (bias) {
                int col = bn + (tx << 3) + 2 * j;
                v.x += bias[col]; v.y += bias[col + 1];
            }
            if (relu) { v.x = fmaxf(v.x, 0.f); v.y = fmaxf(v.y, 0.f); }
            *(float2*)(cp + 2 * j) = v;
        }
    }
}

// ---------------- persistent LSTM scan ----------------
// 128 blocks x 256 threads. Block k owns hidden units [6k, 6k+6).
// SMEM: w_s[768*24], red (8 warps x 32 b x 13 ull pairs), c_s[6*32].
#define SMEM_SCAN_FLOATS (18432 + 6656 + 192)

__device__ __forceinline__ void wait_flags(unsigned target) {
    const unsigned* p = &g_flag[(threadIdx.x & 127) << 5];
    unsigned v;
    do {
        asm volatile("ld.acquire.gpu.u32 %0,[%1];" : "=r"(v) : "l"(p) : "memory");
    } while (v < target);
    __syncthreads();
}

__device__ __forceinline__ void arrive_flag(unsigned val) {
    __syncthreads();      // all gate stores issued before the fence
    if (threadIdx.x == 0) {
        __threadfence();  // drain SM stores to L2
        asm volatile("st.release.gpu.u32 [%0],%1;"
                     :: "l"(&g_flag[blockIdx.x << 5]), "r"(val) : "memory");
    }
}

__device__ __forceinline__ void pre_xg(int t, int tid, int j0, float* xgv) {
    if (tid < 192) {
        int u = tid >> 5, b = tid & 31;
        const float* xp = g_xg + (size_t)(b * T_ + t) * G4 + j0 + u;
        xgv[0] = xp[0];
        xgv[1] = xp[H_];
        xgv[2] = xp[2 * H_];
        xgv[3] = xp[3 * H_];
    }
}

__global__ __launch_bounds__(256)
void scan_kernel(const float* __restrict__ w_hh)
{
    extern __shared__ float sm[];
    float* w_s   = sm;                 // 18432 floats
    float* red_f = sm + 18432;         // 6656 floats (= 8*32*13 ull)
    ull*   red_u = (ull*)red_f;
    float* c_s   = red_f + 6656;       // 192 floats

    const int tid = threadIdx.x, lane = tid & 31, warp = tid >> 5;
    const int j0 = blockIdx.x * 6;

    // load weight slice (persists all 2048 steps)
    for (int idx = tid; idx < 768 * 24; idx += 256) {
        int k = idx / 24, c = idx - k * 24;
        int q = c / 6, u = c - q * 6;
        w_s[idx] = w_hh[(size_t)k * G4 + q * H_ + j0 + u];
    }
    if (tid < 192) {
        c_s[tid] = 0.f;
        int u = tid >> 5, b = tid & 31;
        g_h[0][(j0 + u) * 32 + b] = 0.f;
    }
    arrive_flag(1u);   // h0 slice published

    float xga[4];
    pre_xg(0, tid, j0, xga);

    for (int t = 0; t < T_; t++) {
        const float* hcur = g_h[t & 1];
        float*       hnxt = g_h[(t + 1) & 1];

        wait_flags((unsigned)(t + 1));   // all h_t slices visible

        // prefetch next step's gate inputs (hides DRAM latency under the GEMM)
        float xgb[4];
        pre_xg(t + 1 < T_ ? t + 1 : T_ - 1, tid, j0, xgb);

        // split-K GEMM: warp covers k in [warp*96, warp*96+96), lane = batch b
        ull acc[12];
#pragma unroll
        for (int j = 0; j < 12; j++) acc[j] = 0ull;

        const float* hp  = hcur + warp * 96 * 32 + lane;
        const float* wsp = w_s + warp * 96 * 24;

        float hb[3][8];
#pragma unroll
        for (int i = 0; i < 8; i++) hb[0][i] = __ldcg(hp + i * 32);
#pragma unroll
        for (int i = 0; i < 8; i++) hb[1][i] = __ldcg(hp + (8 + i) * 32);
#pragma unroll
        for (int i = 0; i < 8; i++) hb[2][i] = __ldcg(hp + (16 + i) * 32);

#pragma unroll
        for (int it = 0; it < 12; it++) {
            const float* ha = hb[it % 3];
#pragma unroll
            for (int i = 0; i < 8; i++) {
                ull hv = pk2(ha[i], ha[i]);
                const ulonglong2* wv = (const ulonglong2*)(wsp + (it * 8 + i) * 24);
                ulonglong2 w0 = wv[0], w1 = wv[1], w2 = wv[2];
                ulonglong2 w3 = wv[3], w4 = wv[4], w5 = wv[5];
                fma2(acc[0],  hv, w0.x); fma2(acc[1],  hv, w0.y);
                fma2(acc[2],  hv, w1.x); fma2(acc[3],  hv, w1.y);
                fma2(acc[4],  hv, w2.x); fma2(acc[5],  hv, w2.y);
                fma2(acc[6],  hv, w3.x); fma2(acc[7],  hv, w3.y);
                fma2(acc[8],  hv, w4.x); fma2(acc[9],  hv, w4.y);
                fma2(acc[10], hv, w5.x); fma2(acc[11], hv, w5.y);
            }
            if (it + 3 < 12) {
#pragma unroll
                for (int i = 0; i < 8; i++)
                    hb[it % 3][i] = __ldcg(hp + ((it + 3) * 8 + i) * 32);
            }
        }

        // write split-K partials
        ull* rp = red_u + (size_t)tid * 13;
#pragma unroll
        for (int j = 0; j < 12; j++) rp[j] = acc[j];
        __syncthreads();

        // gate phase: thread (u,b) -> one hidden unit, one batch
        if (tid < 192) {
            int u = tid >> 5, b = tid & 31;
            float pre[4];
#pragma unroll
            for (int q = 0; q < 4; q++) {
                int c = q * 6 + u, p = c >> 1, hs = c & 1;
                float s = xga[q];
#pragma unroll
                for (int w = 0; w < 8; w++)
                    s += red_f[(((w * 32 + b) * 13 + p) << 1) + hs];
                pre[q] = s;
            }
            float ig = sigf(pre[0]);
            float fg = sigf(pre[1]);
            float gg = tanh_(pre[2]);
            float og = sigf(pre[3]);
            float cn = fg * c_s[u * 32 + b] + ig * gg;
            c_s[u * 32 + b] = cn;
            float hn = og * tanh_(cn);
            hnxt[(j0 + u) * 32 + b] = hn;
            g_hs[(size_t)(b * T_ + t) * H_ + j0 + u] = hn;
        }
        arrive_flag((unsigned)(t + 2));

        xga[0] = xgb[0]; xga[1] = xgb[1]; xga[2] = xgb[2]; xga[3] = xgb[3];
    }
}

// ---------------- host launcher ----------------
extern "C" void kernel_launch(void* const* d_in, const int* in_sizes, int n_in,
                              void* d_out, int out_size)
{
    const float* x      = (const float*)d_in[0];
    const float* mels   = (const float*)d_in[1];
    const float* w1     = (const float*)d_in[2];
    const float* b1     = (const float*)d_in[3];
    const float* w2     = (const float*)d_in[4];
    const float* b2     = (const float*)d_in[5];
    const float* w_ih   = (const float*)d_in[6];
    const float* w_hh   = (const float*)d_in[7];
    const float* b_ih   = (const float*)d_in[8];
    const float* b_hh   = (const float*)d_in[9];
    const float* w_proj = (const float*)d_in[10];
    float* out = (float*)d_out;

    float *p_m1, *p_m2, *p_xg, *p_hs, *p_bias;
    cudaGetSymbolAddress((void**)&p_m1,  g_m1);
    cudaGetSymbolAddress((void**)&p_m2,  g_m2);
    cudaGetSymbolAddress((void**)&p_xg,  g_xg);
    cudaGetSymbolAddress((void**)&p_hs,  g_hs);
    cudaGetSymbolAddress((void**)&p_bias, g_bias);

    cudaFuncSetAttribute(scan_kernel, cudaFuncAttributeMaxDynamicSharedMemorySize,
                         SMEM_SCAN_FLOATS * 4);

    // fused bias + flag reset (must precede xg GEMM and scan)
    init_kernel<<<16, 256>>>(b_ih, b_hh);

    // PreNet layer 1: [65536,128] @ [128,256] + b1, relu
    sgemm_kernel<<<dim3(2, 512), 256>>>(mels, 128, mels, 128, 128,
                                        w1, b1, 1, p_m1, 256, 128);
    // PreNet layer 2: [65536,256] @ [256,256] + b2, relu
    sgemm_kernel<<<dim3(2, 512), 256>>>(p_m1, 256, p_m1, 256, 256,
                                        w2, b2, 1, p_m2, 256, 256);
    // xg = concat(x, m2) @ w_ih + (b_ih+b_hh)   [65536,768]x[768,3072]
    sgemm_kernel<<<dim3(24, 512), 256>>>(x, 512, p_m2, 256, 512,
                                         w_ih, p_bias, 0, p_xg, 3072, 768);

    // LSTM recurrence (persistent cooperative kernel)
    scan_kernel<<<128, 256, SMEM_SCAN_FLOATS * 4>>>(w_hh);

    // projection: [65536,768] @ [768,128]
    sgemm_kernel<<<dim3(1, 512), 256>>>(p_hs, 768, p_hs, 768, 768,
                                        w_proj, nullptr, 0, out, 128, 768);
}

// round 4
// speedup vs baseline: 1.1183x; 1.0665x over previous
#include <cuda_runtime.h>
#include <cstdint>

#define BT   65536
#define T_   2048
#define B_   32
#define H_   768
#define G4   3072

typedef unsigned long long ull;

// ---------------- scratch (static device memory; no allocs) ----------------
__device__ float g_m1[(size_t)BT * 256];
__device__ float g_m2[(size_t)BT * 256];
__device__ float g_xg[(size_t)BT * G4];     // [b*T+t][4H]
__device__ float g_hs[(size_t)BT * H_];     // [b*T+t][H]
__device__ float g_h[2][H_ * B_];           // double-buffered h, layout [j][b]
__device__ float g_bias[G4];
__device__ unsigned g_flag[128 * 32];       // per-block flags, 128B stride

// ---------------- f32x2 helpers ----------------
__device__ __forceinline__ ull pk2(float lo, float hi) {
    ull r; asm("mov.b64 %0,{%1,%2};" : "=l"(r) : "f"(lo), "f"(hi)); return r;
}
__device__ __forceinline__ void fma2(ull& d, ull a, ull b) {
    asm("fma.rn.f32x2 %0,%1,%2,%0;" : "+l"(d) : "l"(a), "l"(b));
}
__device__ __forceinline__ float2 upk2(ull v) {
    float lo, hi; asm("mov.b64 {%0,%1},%2;" : "=f"(lo), "=f"(hi) : "l"(v));
    float2 r; r.x = lo; r.y = hi; return r;
}

__device__ __forceinline__ float sigf(float x) {
    return __fdividef(1.f, 1.f + __expf(-x));
}
__device__ __forceinline__ float tanh_(float x) {
    return 2.f * sigf(2.f * x) - 1.f;
}

// ---------------- init: fused bias + flag reset ----------------
__global__ void init_kernel(const float* __restrict__ bi, const float* __restrict__ bh) {
    int i = blockIdx.x * 256 + threadIdx.x;
    if (i < 128 * 32) g_flag[i] = 0u;
    if (i < G4) g_bias[i] = bi[i] + bh[i];
}

// ---------------- generic SGEMM: C[M,N] = concatA[M,K] @ W[K,N] (+bias)(+relu) --------
__device__ __forceinline__ int swz(int c) { return c + ((c >> 5) << 2); }

__global__ __launch_bounds__(256, 2)
void sgemm_kernel(const float* __restrict__ A1, int lda1,
                  const float* __restrict__ A2, int lda2, int split,
                  const float* __restrict__ W,
                  const float* __restrict__ bias, int relu,
                  float* __restrict__ C, int N, int K)
{
    __shared__ float As[16][132];
    __shared__ float Bs[16][144];
    const int tid = threadIdx.x;
    const int tx = tid & 15, ty = tid >> 4;
    const int bm = blockIdx.y << 7, bn = blockIdx.x << 7;

    ull acc[8][4];
#pragma unroll
    for (int i = 0; i < 8; i++)
#pragma unroll
        for (int j = 0; j < 4; j++) acc[i][j] = 0ull;

    const int aq0 = tid, aq1 = tid + 256;
    const int ar0 = aq0 >> 2, ak0 = (aq0 & 3) << 2;
    const int ar1 = aq1 >> 2, ak1 = (aq1 & 3) << 2;
    const int bkk = tid >> 5, bcc = (tid & 31) << 2;

    float4 pa0, pa1, pb0, pb1;

    auto ldTiles = [&](int k0) {
        int kg0 = k0 + ak0;
        pa0 = (kg0 < split)
            ? *(const float4*)(A1 + (size_t)(bm + ar0) * lda1 + kg0)
            : *(const float4*)(A2 + (size_t)(bm + ar0) * lda2 + (kg0 - split));
        int kg1 = k0 + ak1;
        pa1 = (kg1 < split)
            ? *(const float4*)(A1 + (size_t)(bm + ar1) * lda1 + kg1)
            : *(const float4*)(A2 + (size_t)(bm + ar1) * lda2 + (kg1 - split));
        pb0 = *(const float4*)(W + (size_t)(k0 + bkk) * N + bn + bcc);
        pb1 = *(const float4*)(W + (size_t)(k0 + bkk + 8) * N + bn + bcc);
    };
    auto stTiles = [&]() {
        As[ak0 + 0][ar0] = pa0.x; As[ak0 + 1][ar0] = pa0.y;
        As[ak0 + 2][ar0] = pa0.z; As[ak0 + 3][ar0] = pa0.w;
        As[ak1 + 0][ar1] = pa1.x; As[ak1 + 1][ar1] = pa1.y;
        As[ak1 + 2][ar1] = pa1.z; As[ak1 + 3][ar1] = pa1.w;
        *(float4*)&Bs[bkk][swz(bcc)] = pb0;
        *(float4*)&Bs[bkk + 8][swz(bcc)] = pb1;
    };
    auto comp = [&]() {
#pragma unroll
        for (int kk = 0; kk < 16; kk++) {
            float4 a0 = *(const float4*)&As[kk][ty << 3];
            float4 a1 = *(const float4*)&As[kk][(ty << 3) + 4];
            ulonglong2 b01 = *(const ulonglong2*)&Bs[kk][swz(tx << 3)];
            ulonglong2 b23 = *(const ulonglong2*)&Bs[kk][swz((tx << 3) + 4)];
            float ar[8] = {a0.x, a0.y, a0.z, a0.w, a1.x, a1.y, a1.z, a1.w};
#pragma unroll
            for (int i = 0; i < 8; i++) {
                ull av = pk2(ar[i], ar[i]);
                fma2(acc[i][0], av, b01.x);
                fma2(acc[i][1], av, b01.y);
                fma2(acc[i][2], av, b23.x);
                fma2(acc[i][3], av, b23.y);
            }
        }
    };

    ldTiles(0);
    stTiles();
    __syncthreads();
    for (int k0 = 0; k0 < K; k0 += 16) {
        bool more = (k0 + 16) < K;
        if (more) ldTiles(k0 + 16);
        comp();
        __syncthreads();
        if (more) { stTiles(); __syncthreads(); }
    }

#pragma unroll
    for (int i = 0; i < 8; i++) {
        int row = bm + (ty << 3) + i;
        float* cp = C + (size_t)row * N + bn + (tx << 3);
#pragma unroll
        for (int j = 0; j < 4; j++) {
            float2 v = upk2(acc[i][j]);
            if (bias) {
                int col = bn + (tx << 3) + 2 * j;
                v.x += bias[col]; v.y += bias[col + 1];
            }
            if (relu) { v.x = fmaxf(v.x, 0.f); v.y = fmaxf(v.y, 0.f); }
            *(float2*)(cp + 2 * j) = v;
        }
    }
}

// ---------------- persistent LSTM scan ----------------
// 128 blocks x 512 threads (16 warps). Block k owns hidden units [6k, 6k+6).
// warp w covers k in [w*48, w*48+48), lane = batch b.
// SMEM: w_s[768*24], red (16 warps x 32 b x 13 ull), c_s[6*32].
#define SMEM_SCAN_FLOATS (18432 + 13312 + 192)

__device__ __forceinline__ void wait_flags(unsigned target) {
    // warp 0 polls: thread i watches flags[4i .. 4i+3]
    if (threadIdx.x < 32) {
        const unsigned* p0 = &g_flag[(threadIdx.x * 4 + 0) << 5];
        const unsigned* p1 = &g_flag[(threadIdx.x * 4 + 1) << 5];
        const unsigned* p2 = &g_flag[(threadIdx.x * 4 + 2) << 5];
        const unsigned* p3 = &g_flag[(threadIdx.x * 4 + 3) << 5];
        unsigned v0, v1, v2, v3;
        do {
            asm volatile("ld.acquire.gpu.u32 %0,[%1];" : "=r"(v0) : "l"(p0) : "memory");
            asm volatile("ld.acquire.gpu.u32 %0,[%1];" : "=r"(v1) : "l"(p1) : "memory");
            asm volatile("ld.acquire.gpu.u32 %0,[%1];" : "=r"(v2) : "l"(p2) : "memory");
            asm volatile("ld.acquire.gpu.u32 %0,[%1];" : "=r"(v3) : "l"(p3) : "memory");
        } while (v0 < target || v1 < target || v2 < target || v3 < target);
    }
    __syncthreads();
}

__device__ __forceinline__ void pre_xg(int t, int tid, int j0, float* xgv) {
    if (tid < 192) {
        int u = tid >> 5, b = tid & 31;
        const float* xp = g_xg + (size_t)(b * T_ + t) * G4 + j0 + u;
        xgv[0] = __ldcg(xp);
        xgv[1] = __ldcg(xp + H_);
        xgv[2] = __ldcg(xp + 2 * H_);
        xgv[3] = __ldcg(xp + 3 * H_);
    }
}

__global__ __launch_bounds__(512, 1)
void scan_kernel(const float* __restrict__ w_hh)
{
    extern __shared__ float sm[];
    float* w_s   = sm;                  // 18432 floats
    float* red_f = sm + 18432;          // 13312 floats (= 16*32*13 ull)
    ull*   red_u = (ull*)red_f;
    float* c_s   = red_f + 13312;       // 192 floats

    const int tid = threadIdx.x, lane = tid & 31, warp = tid >> 5;
    const int j0 = blockIdx.x * 6;

    // load weight slice (persists all 2048 steps)
    for (int idx = tid; idx < 768 * 24; idx += 512) {
        int k = idx / 24, c = idx - k * 24;
        int q = c / 6, u = c - q * 6;
        w_s[idx] = w_hh[(size_t)k * G4 + q * H_ + j0 + u];
    }
    if (tid < 192) {
        c_s[tid] = 0.f;
        int u = tid >> 5, b = tid & 31;
        g_h[0][(j0 + u) * 32 + b] = 0.f;
    }
    __syncthreads();
    if (tid == 0) {
        __threadfence();
        asm volatile("st.release.gpu.u32 [%0],%1;"
                     :: "l"(&g_flag[blockIdx.x << 5]), "r"(1u) : "memory");
    }

    float xga[4];
    pre_xg(0, tid, j0, xga);

    for (int t = 0; t < T_; t++) {
        const float* hcur = g_h[t & 1];
        float*       hnxt = g_h[(t + 1) & 1];

        wait_flags((unsigned)(t + 1));   // all h_t slices visible

        // prefetch next step's gate inputs
        float xgb[4];
        pre_xg(t + 1 < T_ ? t + 1 : T_ - 1, tid, j0, xgb);

        // GEMM: warp covers 48 k-values; issue all h loads up-front (max MLP)
        const float* hp  = hcur + warp * 48 * 32 + lane;
        const float* wsp = w_s + warp * 48 * 24;

        float hv_all[48];
#pragma unroll
        for (int i = 0; i < 48; i++) hv_all[i] = __ldcg(hp + i * 32);

        ull acc[12];
#pragma unroll
        for (int j = 0; j < 12; j++) acc[j] = 0ull;

#pragma unroll
        for (int k = 0; k < 48; k++) {
            ull hv = pk2(hv_all[k], hv_all[k]);
            const ulonglong2* wv = (const ulonglong2*)(wsp + k * 24);
            ulonglong2 w0 = wv[0], w1 = wv[1], w2 = wv[2];
            ulonglong2 w3 = wv[3], w4 = wv[4], w5 = wv[5];
            fma2(acc[0],  hv, w0.x); fma2(acc[1],  hv, w0.y);
            fma2(acc[2],  hv, w1.x); fma2(acc[3],  hv, w1.y);
            fma2(acc[4],  hv, w2.x); fma2(acc[5],  hv, w2.y);
            fma2(acc[6],  hv, w3.x); fma2(acc[7],  hv, w3.y);
            fma2(acc[8],  hv, w4.x); fma2(acc[9],  hv, w4.y);
            fma2(acc[10], hv, w5.x); fma2(acc[11], hv, w5.y);
        }

        // write split-K partials
        ull* rp = red_u + (size_t)tid * 13;
#pragma unroll
        for (int j = 0; j < 12; j++) rp[j] = acc[j];
        __syncthreads();

        // gate phase: thread (u,b) -> one hidden unit, one batch
        float hn = 0.f;
        if (tid < 192) {
            int u = tid >> 5, b = tid & 31;
            float pre[4];
#pragma unroll
            for (int q = 0; q < 4; q++) {
                int c = q * 6 + u, p = c >> 1, hs = c & 1;
                float s0 = xga[q], s1 = 0.f, s2 = 0.f, s3 = 0.f;
#pragma unroll
                for (int w = 0; w < 16; w += 4) {
                    s0 += red_f[((((w + 0) * 32 + b) * 13 + p) << 1) + hs];
                    s1 += red_f[((((w + 1) * 32 + b) * 13 + p) << 1) + hs];
                    s2 += red_f[((((w + 2) * 32 + b) * 13 + p) << 1) + hs];
                    s3 += red_f[((((w + 3) * 32 + b) * 13 + p) << 1) + hs];
                }
                pre[q] = (s0 + s1) + (s2 + s3);
            }
            float ig = sigf(pre[0]);
            float fg = sigf(pre[1]);
            float gg = tanh_(pre[2]);
            float og = sigf(pre[3]);
            float cn = fg * c_s[u * 32 + b] + ig * gg;
            c_s[u * 32 + b] = cn;
            hn = og * tanh_(cn);
            hnxt[(j0 + u) * 32 + b] = hn;   // coalesced 768B publish
        }
        __syncthreads();   // all h stores issued
        if (tid == 0) {
            __threadfence();
            asm volatile("st.release.gpu.u32 [%0],%1;"
                         :: "l"(&g_flag[blockIdx.x << 5]), "r"((unsigned)(t + 2)) : "memory");
        }

        // off-critical-path: scattered hs store AFTER the flag release
        if (tid < 192) {
            int u = tid >> 5, b = tid & 31;
            g_hs[(size_t)(b * T_ + t) * H_ + j0 + u] = hn;
        }

        xga[0] = xgb[0]; xga[1] = xgb[1]; xga[2] = xgb[2]; xga[3] = xgb[3];
    }
}

// ---------------- host launcher ----------------
extern "C" void kernel_launch(void* const* d_in, const int* in_sizes, int n_in,
                              void* d_out, int out_size)
{
    const float* x      = (const float*)d_in[0];
    const float* mels   = (const float*)d_in[1];
    const float* w1     = (const float*)d_in[2];
    const float* b1     = (const float*)d_in[3];
    const float* w2     = (const float*)d_in[4];
    const float* b2     = (const float*)d_in[5];
    const float* w_ih   = (const float*)d_in[6];
    const float* w_hh   = (const float*)d_in[7];
    const float* b_ih   = (const float*)d_in[8];
    const float* b_hh   = (const float*)d_in[9];
    const float* w_proj = (const float*)d_in[10];
    float* out = (float*)d_out;

    float *p_m1, *p_m2, *p_xg, *p_hs, *p_bias;
    cudaGetSymbolAddress((void**)&p_m1,  g_m1);
    cudaGetSymbolAddress((void**)&p_m2,  g_m2);
    cudaGetSymbolAddress((void**)&p_xg,  g_xg);
    cudaGetSymbolAddress((void**)&p_hs,  g_hs);
    cudaGetSymbolAddress((void**)&p_bias, g_bias);

    cudaFuncSetAttribute(scan_kernel, cudaFuncAttributeMaxDynamicSharedMemorySize,
                         SMEM_SCAN_FLOATS * 4);

    // fused bias + flag reset (must precede xg GEMM and scan)
    init_kernel<<<16, 256>>>(b_ih, b_hh);

    // PreNet layer 1: [65536,128] @ [128,256] + b1, relu
    sgemm_kernel<<<dim3(2, 512), 256>>>(mels, 128, mels, 128, 128,
                                        w1, b1, 1, p_m1, 256, 128);
    // PreNet layer 2: [65536,256] @ [256,256] + b2, relu
    sgemm_kernel<<<dim3(2, 512), 256>>>(p_m1, 256, p_m1, 256, 256,
                                        w2, b2, 1, p_m2, 256, 256);
    // xg = concat(x, m2) @ w_ih + (b_ih+b_hh)   [65536,768]x[768,3072]
    sgemm_kernel<<<dim3(24, 512), 256>>>(x, 512, p_m2, 256, 512,
                                         w_ih, p_bias, 0, p_xg, 3072, 768);

    // LSTM recurrence (persistent cooperative kernel)
    scan_kernel<<<128, 512, SMEM_SCAN_FLOATS * 4>>>(w_hh);

    // projection: [65536,768] @ [768,128]
    sgemm_kernel<<<dim3(1, 512), 256>>>(p_hs, 768, p_hs, 768, 768,
                                        w_proj, nullptr, 0, out, 128, 768);
}

// round 5
// speedup vs baseline: 1.3562x; 1.2127x over previous
#include <cuda_runtime.h>
#include <cstdint>

#define BT   65536
#define T_   2048
#define B_   32
#define H_   768
#define G4   3072

typedef unsigned long long ull;

// ---------------- scratch (static device memory; no allocs) ----------------
__device__ float g_m1[(size_t)BT * 256];
__device__ float g_m2[(size_t)BT * 256];
__device__ float g_xg[(size_t)BT * G4];     // [b*T+t][4H]
__device__ float g_hs[(size_t)BT * H_];     // [b*T+t][H]
__device__ float g_h[2][H_ * B_];           // double-buffered h, layout [j][b]
__device__ float g_bias[G4];
__device__ unsigned g_flag[128 * 32];       // per-block flags, 128B stride

// ---------------- f32x2 helpers ----------------
__device__ __forceinline__ ull pk2(float lo, float hi) {
    ull r; asm("mov.b64 %0,{%1,%2};" : "=l"(r) : "f"(lo), "f"(hi)); return r;
}
__device__ __forceinline__ void fma2(ull& d, ull a, ull b) {
    asm("fma.rn.f32x2 %0,%1,%2,%0;" : "+l"(d) : "l"(a), "l"(b));
}
__device__ __forceinline__ float2 upk2(ull v) {
    float lo, hi; asm("mov.b64 {%0,%1},%2;" : "=f"(lo), "=f"(hi) : "l"(v));
    float2 r; r.x = lo; r.y = hi; return r;
}

__device__ __forceinline__ float sigf(float x) {
    return __fdividef(1.f, 1.f + __expf(-x));
}
__device__ __forceinline__ float tanh_(float x) {
    return 2.f * sigf(2.f * x) - 1.f;
}

// ---------------- init: fused bias + flag reset ----------------
__global__ void init_kernel(const float* __restrict__ bi, const float* __restrict__ bh) {
    int i = blockIdx.x * 256 + threadIdx.x;
    if (i < 128 * 32) g_flag[i] = 0u;
    if (i < G4) g_bias[i] = bi[i] + bh[i];
}

// ---------------- generic SGEMM: C[M,N] = concatA[M,K] @ W[K,N] (+bias)(+relu) --------
__device__ __forceinline__ int swz(int c) { return c + ((c >> 5) << 2); }

__global__ __launch_bounds__(256, 2)
void sgemm_kernel(const float* __restrict__ A1, int lda1,
                  const float* __restrict__ A2, int lda2, int split,
                  const float* __restrict__ W,
                  const float* __restrict__ bias, int relu,
                  float* __restrict__ C, int N, int K)
{
    __shared__ float As[16][132];
    __shared__ float Bs[16][144];
    const int tid = threadIdx.x;
    const int tx = tid & 15, ty = tid >> 4;
    const int bm = blockIdx.y << 7, bn = blockIdx.x << 7;

    ull acc[8][4];
#pragma unroll
    for (int i = 0; i < 8; i++)
#pragma unroll
        for (int j = 0; j < 4; j++) acc[i][j] = 0ull;

    const int aq0 = tid, aq1 = tid + 256;
    const int ar0 = aq0 >> 2, ak0 = (aq0 & 3) << 2;
    const int ar1 = aq1 >> 2, ak1 = (aq1 & 3) << 2;
    const int bkk = tid >> 5, bcc = (tid & 31) << 2;

    float4 pa0, pa1, pb0, pb1;

    auto ldTiles = [&](int k0) {
        int kg0 = k0 + ak0;
        pa0 = (kg0 < split)
            ? *(const float4*)(A1 + (size_t)(bm + ar0) * lda1 + kg0)
            : *(const float4*)(A2 + (size_t)(bm + ar0) * lda2 + (kg0 - split));
        int kg1 = k0 + ak1;
        pa1 = (kg1 < split)
            ? *(const float4*)(A1 + (size_t)(bm + ar1) * lda1 + kg1)
            : *(const float4*)(A2 + (size_t)(bm + ar1) * lda2 + (kg1 - split));
        pb0 = *(const float4*)(W + (size_t)(k0 + bkk) * N + bn + bcc);
        pb1 = *(const float4*)(W + (size_t)(k0 + bkk + 8) * N + bn + bcc);
    };
    auto stTiles = [&]() {
        As[ak0 + 0][ar0] = pa0.x; As[ak0 + 1][ar0] = pa0.y;
        As[ak0 + 2][ar0] = pa0.z; As[ak0 + 3][ar0] = pa0.w;
        As[ak1 + 0][ar1] = pa1.x; As[ak1 + 1][ar1] = pa1.y;
        As[ak1 + 2][ar1] = pa1.z; As[ak1 + 3][ar1] = pa1.w;
        *(float4*)&Bs[bkk][swz(bcc)] = pb0;
        *(float4*)&Bs[bkk + 8][swz(bcc)] = pb1;
    };
    auto comp = [&]() {
#pragma unroll
        for (int kk = 0; kk < 16; kk++) {
            float4 a0 = *(const float4*)&As[kk][ty << 3];
            float4 a1 = *(const float4*)&As[kk][(ty << 3) + 4];
            ulonglong2 b01 = *(const ulonglong2*)&Bs[kk][swz(tx << 3)];
            ulonglong2 b23 = *(const ulonglong2*)&Bs[kk][swz((tx << 3) + 4)];
            float ar[8] = {a0.x, a0.y, a0.z, a0.w, a1.x, a1.y, a1.z, a1.w};
#pragma unroll
            for (int i = 0; i < 8; i++) {
                ull av = pk2(ar[i], ar[i]);
                fma2(acc[i][0], av, b01.x);
                fma2(acc[i][1], av, b01.y);
                fma2(acc[i][2], av, b23.x);
                fma2(acc[i][3], av, b23.y);
            }
        }
    };

    ldTiles(0);
    stTiles();
    __syncthreads();
    for (int k0 = 0; k0 < K; k0 += 16) {
        bool more = (k0 + 16) < K;
        if (more) ldTiles(k0 + 16);
        comp();
        __syncthreads();
        if (more) { stTiles(); __syncthreads(); }
    }

#pragma unroll
    for (int i = 0; i < 8; i++) {
        int row = bm + (ty << 3) + i;
        float* cp = C + (size_t)row * N + bn + (tx << 3);
#pragma unroll
        for (int j = 0; j < 4; j++) {
            float2 v = upk2(acc[i][j]);
            if (bias) {
                int col = bn + (tx << 3) + 2 * j;
                v.x += bias[col]; v.y += bias[col + 1];
            }
            if (relu) { v.x = fmaxf(v.x, 0.f); v.y = fmaxf(v.y, 0.f); }
            *(float2*)(cp + 2 * j) = v;
        }
    }
}

// ---------------- persistent LSTM scan ----------------
// 128 blocks x 512 threads (16 warps). Block k owns hidden units [6k, 6k+6).
// warp w covers k in [w*48, w*48+48) -> producer blocks [8w, 8w+8).
// SMEM: w_s[768*24], red (512 threads x 25 floats, stride-25 conflict-free), c_s[6*32].
#define SMEM_SCAN_FLOATS (18432 + 12800 + 192)

__device__ __forceinline__ void pre_xg(int t, int tid, int j0, float* xgv) {
    if (tid < 192) {
        int u = tid >> 5, b = tid & 31;
        const float* xp = g_xg + (size_t)(b * T_ + t) * G4 + j0 + u;
        xgv[0] = __ldcg(xp);
        xgv[1] = __ldcg(xp + H_);
        xgv[2] = __ldcg(xp + 2 * H_);
        xgv[3] = __ldcg(xp + 3 * H_);
    }
}

__global__ __launch_bounds__(512, 1)
void scan_kernel(const float* __restrict__ w_hh)
{
    extern __shared__ float sm[];
    float* w_s   = sm;                  // 18432 floats
    float* red_f = sm + 18432;          // 12800 floats (512 x 25)
    float* c_s   = red_f + 12800;       // 192 floats

    const int tid = threadIdx.x, lane = tid & 31, warp = tid >> 5;
    const int j0 = blockIdx.x * 6;

    // load weight slice (persists all 2048 steps)
    for (int idx = tid; idx < 768 * 24; idx += 512) {
        int k = idx / 24, c = idx - k * 24;
        int q = c / 6, u = c - q * 6;
        w_s[idx] = w_hh[(size_t)k * G4 + q * H_ + j0 + u];
    }
    if (tid < 192) {
        c_s[tid] = 0.f;
        int u = tid >> 5, b = tid & 31;
        g_h[0][(j0 + u) * 32 + b] = 0.f;
    }
    __syncthreads();
    if (tid == 0) {
        __threadfence();
        asm volatile("st.release.gpu.u32 [%0],%1;"
                     :: "l"(&g_flag[blockIdx.x << 5]), "r"(1u) : "memory");
    }

    // per-warp flag pointer: lanes 0..7 watch this warp's 8 producer blocks
    const unsigned* fp = &g_flag[((warp << 3) + (lane & 7)) << 5];

    float xga[4];
    pre_xg(0, tid, j0, xga);

    for (int t = 0; t < T_; t++) {
        const float* hcur = g_h[t & 1];
        float*       hnxt = g_h[(t + 1) & 1];
        const unsigned target = (unsigned)(t + 1);

        // per-warp wait: only this warp's 8 producers must have published h_t
        unsigned v;
        do {
            asm volatile("ld.acquire.gpu.u32 %0,[%1];" : "=r"(v) : "l"(fp) : "memory");
        } while (!__all_sync(0xffffffffu, v >= target));

        // prefetch next step's gate inputs (hidden under the GEMM)
        float xgb[4];
        pre_xg(t + 1 < T_ ? t + 1 : T_ - 1, tid, j0, xgb);

        // GEMM: warp covers 48 k-values, chunked 4x12 with 2 rotating buffers
        const float* hp  = hcur + warp * 48 * 32 + lane;
        const float* wsp = w_s + warp * 48 * 24;

        float bufA[12], bufB[12];
#pragma unroll
        for (int i = 0; i < 12; i++) bufA[i] = __ldcg(hp + i * 32);
#pragma unroll
        for (int i = 0; i < 12; i++) bufB[i] = __ldcg(hp + (12 + i) * 32);

        ull acc[12];
#pragma unroll
        for (int j = 0; j < 12; j++) acc[j] = 0ull;

#pragma unroll
        for (int c = 0; c < 4; c++) {
            float* cur = (c & 1) ? bufB : bufA;
#pragma unroll
            for (int i = 0; i < 12; i++) {
                int k = c * 12 + i;
                ull hv = pk2(cur[i], cur[i]);
                const ulonglong2* wv = (const ulonglong2*)(wsp + k * 24);
                ulonglong2 w0 = wv[0], w1 = wv[1], w2 = wv[2];
                ulonglong2 w3 = wv[3], w4 = wv[4], w5 = wv[5];
                fma2(acc[0],  hv, w0.x); fma2(acc[1],  hv, w0.y);
                fma2(acc[2],  hv, w1.x); fma2(acc[3],  hv, w1.y);
                fma2(acc[4],  hv, w2.x); fma2(acc[5],  hv, w2.y);
                fma2(acc[6],  hv, w3.x); fma2(acc[7],  hv, w3.y);
                fma2(acc[8],  hv, w4.x); fma2(acc[9],  hv, w4.y);
                fma2(acc[10], hv, w5.x); fma2(acc[11], hv, w5.y);
            }
            if (c < 2) {
#pragma unroll
                for (int i = 0; i < 12; i++)
                    cur[i] = __ldcg(hp + ((c + 2) * 12 + i) * 32);
            }
        }

        // write split-K partials (stride 25 floats: conflict-free both directions)
        {
            float* rp = red_f + tid * 25;
#pragma unroll
            for (int j = 0; j < 12; j++) {
                float2 v = upk2(acc[j]);
                rp[2 * j]     = v.x;
                rp[2 * j + 1] = v.y;
            }
        }
        __syncthreads();

        // gate phase: thread (u,b) -> one hidden unit, one batch
        float hn = 0.f;
        if (tid < 192) {
            int u = tid >> 5, b = tid & 31;
            float pre[4];
#pragma unroll
            for (int q = 0; q < 4; q++) {
                int c = q * 6 + u;
                const float* rb = red_f + b * 25 + c;
                float s0 = xga[q], s1 = 0.f, s2 = 0.f, s3 = 0.f;
#pragma unroll
                for (int w = 0; w < 16; w += 4) {
                    s0 += rb[(w + 0) * 32 * 25];
                    s1 += rb[(w + 1) * 32 * 25];
                    s2 += rb[(w + 2) * 32 * 25];
                    s3 += rb[(w + 3) * 32 * 25];
                }
                pre[q] = (s0 + s1) + (s2 + s3);
            }
            float ig = sigf(pre[0]);
            float fg = sigf(pre[1]);
            float gg = tanh_(pre[2]);
            float og = sigf(pre[3]);
            float cn = fg * c_s[u * 32 + b] + ig * gg;
            c_s[u * 32 + b] = cn;
            hn = og * tanh_(cn);
            hnxt[(j0 + u) * 32 + b] = hn;   // coalesced 768B publish
        }
        __syncthreads();   // all h stores issued
        if (tid == 0) {
            __threadfence();
            asm volatile("st.release.gpu.u32 [%0],%1;"
                         :: "l"(&g_flag[blockIdx.x << 5]), "r"((unsigned)(t + 2)) : "memory");
        }

        // off-critical-path: scattered hs store AFTER the flag release
        if (tid < 192) {
            int u = tid >> 5, b = tid & 31;
            g_hs[(size_t)(b * T_ + t) * H_ + j0 + u] = hn;
        }

        xga[0] = xgb[0]; xga[1] = xgb[1]; xga[2] = xgb[2]; xga[3] = xgb[3];
    }
}

// ---------------- host launcher ----------------
extern "C" void kernel_launch(void* const* d_in, const int* in_sizes, int n_in,
                              void* d_out, int out_size)
{
    const float* x      = (const float*)d_in[0];
    const float* mels   = (const float*)d_in[1];
    const float* w1     = (const float*)d_in[2];
    const float* b1     = (const float*)d_in[3];
    const float* w2     = (const float*)d_in[4];
    const float* b2     = (const float*)d_in[5];
    const float* w_ih   = (const float*)d_in[6];
    const float* w_hh   = (const float*)d_in[7];
    const float* b_ih   = (const float*)d_in[8];
    const float* b_hh   = (const float*)d_in[9];
    const float* w_proj = (const float*)d_in[10];
    float* out = (float*)d_out;

    float *p_m1, *p_m2, *p_xg, *p_hs, *p_bias;
    cudaGetSymbolAddress((void**)&p_m1,  g_m1);
    cudaGetSymbolAddress((void**)&p_m2,  g_m2);
    cudaGetSymbolAddress((void**)&p_xg,  g_xg);
    cudaGetSymbolAddress((void**)&p_hs,  g_hs);
    cudaGetSymbolAddress((void**)&p_bias, g_bias);

    cudaFuncSetAttribute(scan_kernel, cudaFuncAttributeMaxDynamicSharedMemorySize,
                         SMEM_SCAN_FLOATS * 4);

    // fused bias + flag reset (must precede xg GEMM and scan)
    init_kernel<<<16, 256>>>(b_ih, b_hh);

    // PreNet layer 1: [65536,128] @ [128,256] + b1, relu
    sgemm_kernel<<<dim3(2, 512), 256>>>(mels, 128, mels, 128, 128,
                                        w1, b1, 1, p_m1, 256, 128);
    // PreNet layer 2: [65536,256] @ [256,256] + b2, relu
    sgemm_kernel<<<dim3(2, 512), 256>>>(p_m1, 256, p_m1, 256, 256,
                                        w2, b2, 1, p_m2, 256, 256);
    // xg = concat(x, m2) @ w_ih + (b_ih+b_hh)   [65536,768]x[768,3072]
    sgemm_kernel<<<dim3(24, 512), 256>>>(x, 512, p_m2, 256, 512,
                                         w_ih, p_bias, 0, p_xg, 3072, 768);

    // LSTM recurrence (persistent cooperative kernel)
    scan_kernel<<<128, 512, SMEM_SCAN_FLOATS * 4>>>(w_hh);

    // projection: [65536,768] @ [768,128]
    sgemm_kernel<<<dim3(1, 512), 256>>>(p_hs, 768, p_hs, 768, 768,
                                        w_proj, nullptr, 0, out, 128, 768);
}

// round 7
// speedup vs baseline: 1.4308x; 1.0550x over previous
#include <cuda_runtime.h>
#include <mma.h>
#include <cstdint>

using namespace nvcuda;

#define BT   65536
#define T_   2048
#define B_   32
#define H_   768
#define G4   3072

typedef unsigned long long ull;

// ---------------- scratch (static device memory; no allocs) ----------------
__device__ float g_m1[(size_t)BT * 256];
__device__ float g_m2[(size_t)BT * 256];
__device__ float g_xg[(size_t)BT * G4];     // [b*T+t][4H]
__device__ float g_hs[(size_t)BT * H_];     // [b*T+t][H]
__device__ float g_h[2][H_ * B_];           // double-buffered h, layout [j][b]
__device__ float g_bias[G4];
__device__ unsigned g_flag[128 * 32];       // per-block flags, 128B stride

// ---------------- helpers ----------------
__device__ __forceinline__ ull pk2(float lo, float hi) {
    ull r; asm("mov.b64 %0,{%1,%2};" : "=l"(r) : "f"(lo), "f"(hi)); return r;
}
__device__ __forceinline__ void fma2(ull& d, ull a, ull b) {
    asm("fma.rn.f32x2 %0,%1,%2,%0;" : "+l"(d) : "l"(a), "l"(b));
}
__device__ __forceinline__ float2 upk2(ull v) {
    float lo, hi; asm("mov.b64 {%0,%1},%2;" : "=f"(lo), "=f"(hi) : "l"(v));
    float2 r; r.x = lo; r.y = hi; return r;
}
__device__ __forceinline__ float sigf(float x) {
    return __fdividef(1.f, 1.f + __expf(-x));
}
__device__ __forceinline__ float tanh_(float x) {
    return 2.f * sigf(2.f * x) - 1.f;
}
__device__ __forceinline__ uint32_t smem_u32(const void* p) {
    uint32_t a;
    asm("{ .reg .u64 t; cvta.to.shared.u64 t, %1; cvt.u32.u64 %0, t; }" : "=r"(a) : "l"(p));
    return a;
}

// ---------------- init: fused bias + flag reset ----------------
__global__ void init_kernel(const float* __restrict__ bi, const float* __restrict__ bh) {
    int i = blockIdx.x * 256 + threadIdx.x;
    if (i < 128 * 32) g_flag[i] = 0u;
    if (i < G4) g_bias[i] = bi[i] + bh[i];
}

// ---------------- tf32 WMMA GEMM for xg ----------------
// C[65536,3072] = concat(x[.,512], m2[.,256]) @ W[768,3072] + bias
// Tile M=128, N=128, K-chunk=32 (24 chunks), cp.async double buffer.
// SMEM floats: As 2*128*36, Bs 2*32*132, bias tile 16*128.
#define XA_LD 36
#define XB_LD 132
#define XS_A  (128 * XA_LD)            // 4608 per buffer
#define XS_B  (32 * XB_LD)             // 4224 per buffer
#define XS_BIAS_OFF (2 * XS_A + 2 * XS_B)
#define XS_TOTAL (XS_BIAS_OFF + 16 * 128)   // 19712 floats = 78848 B

__global__ __launch_bounds__(256, 2)
void xg_wmma_kernel(const float* __restrict__ x, const float* __restrict__ m2p,
                    const float* __restrict__ W)
{
    extern __shared__ float xsm[];
    float* As     = xsm;
    float* Bs     = xsm + 2 * XS_A;
    float* bias_s = xsm + XS_BIAS_OFF;

    const int tid = threadIdx.x;
    const int warp = tid >> 5;
    const int bm = blockIdx.y * 128, bn = blockIdx.x * 128;
    const int wm = (warp & 3) * 32;    // warp row offset in tile
    const int wn = (warp >> 2) * 64;   // warp col offset in tile

    // bias broadcast tile: 16 identical rows of bias[bn..bn+128)
    for (int i = tid; i < 16 * 128; i += 256)
        bias_s[i] = g_bias[bn + (i & 127)];

    wmma::fragment<wmma::accumulator, 16, 16, 8, float> acc[2][4];
#pragma unroll
    for (int i = 0; i < 2; i++)
#pragma unroll
        for (int j = 0; j < 4; j++) wmma::fill_fragment(acc[i][j], 0.f);

    auto cp_tile = [&](int t, int buf) {
        const int kf = t * 32;
        float* ad = As + buf * XS_A;
#pragma unroll
        for (int i = 0; i < 4; i++) {
            int c = tid + 256 * i;
            int row = c >> 3, kc = (c & 7) * 4;
            int kg = kf + kc;
            const float* src = (kg < 512)
                ? (x   + (size_t)(bm + row) * 512 + kg)
                : (m2p + (size_t)(bm + row) * 256 + (kg - 512));
            uint32_t d = smem_u32(ad + row * XA_LD + kc);
            asm volatile("cp.async.cg.shared.global [%0],[%1],16;" :: "r"(d), "l"(src));
        }
        float* bd = Bs + buf * XS_B;
#pragma unroll
        for (int i = 0; i < 4; i++) {
            int c = tid + 256 * i;
            int kr = c >> 5, nc = (c & 31) * 4;
            const float* src = W + (size_t)(kf + kr) * G4 + bn + nc;
            uint32_t d = smem_u32(bd + kr * XB_LD + nc);
            asm volatile("cp.async.cg.shared.global [%0],[%1],16;" :: "r"(d), "l"(src));
        }
    };

    cp_tile(0, 0);
    asm volatile("cp.async.commit_group;" ::: "memory");

    for (int t = 0; t < 24; t++) {
        if (t + 1 < 24) {
            cp_tile(t + 1, (t + 1) & 1);
            asm volatile("cp.async.commit_group;" ::: "memory");
            asm volatile("cp.async.wait_group 1;" ::: "memory");
        } else {
            asm volatile("cp.async.wait_group 0;" ::: "memory");
        }
        __syncthreads();

        const float* At = As + (t & 1) * XS_A + wm * XA_LD;
        const float* Bt = Bs + (t & 1) * XS_B + wn;
#pragma unroll
        for (int ks = 0; ks < 4; ks++) {
            wmma::fragment<wmma::matrix_a, 16, 16, 8, wmma::precision::tf32,
                           wmma::row_major> af[2];
            wmma::fragment<wmma::matrix_b, 16, 16, 8, wmma::precision::tf32,
                           wmma::row_major> bf[4];
#pragma unroll
            for (int i = 0; i < 2; i++) {
                wmma::load_matrix_sync(af[i], At + i * 16 * XA_LD + ks * 8, XA_LD);
#pragma unroll
                for (int e = 0; e < af[i].num_elements; e++)
                    af[i].x[e] = wmma::__float_to_tf32(af[i].x[e]);
            }
#pragma unroll
            for (int j = 0; j < 4; j++) {
                wmma::load_matrix_sync(bf[j], Bt + ks * 8 * XB_LD + j * 16, XB_LD);
#pragma unroll
                for (int e = 0; e < bf[j].num_elements; e++)
                    bf[j].x[e] = wmma::__float_to_tf32(bf[j].x[e]);
            }
#pragma unroll
            for (int i = 0; i < 2; i++)
#pragma unroll
                for (int j = 0; j < 4; j++)
                    wmma::mma_sync(acc[i][j], af[i], bf[j], acc[i][j]);
        }
        __syncthreads();   // protect buf (t&1) before iter t+1 overwrites buf (t+2)&1 == t&1
    }

    // epilogue: add bias (broadcast tile as accumulator fragment), store
    const int row0 = bm + wm, col0 = bn + wn;
#pragma unroll
    for (int i = 0; i < 2; i++)
#pragma unroll
        for (int j = 0; j < 4; j++) {
            wmma::fragment<wmma::accumulator, 16, 16, 8, float> bfr;
            wmma::load_matrix_sync(bfr, bias_s + wn + j * 16, 128, wmma::mem_row_major);
#pragma unroll
            for (int e = 0; e < bfr.num_elements; e++)
                acc[i][j].x[e] += bfr.x[e];
            wmma::store_matrix_sync(g_xg + (size_t)(row0 + i * 16) * G4 + col0 + j * 16,
                                    acc[i][j], G4, wmma::mem_row_major);
        }
}

// ---------------- generic fp32 SGEMM (prenet + proj) ----------------
__device__ __forceinline__ int swz(int c) { return c + ((c >> 5) << 2); }

__global__ __launch_bounds__(256, 2)
void sgemm_kernel(const float* __restrict__ A1, int lda1,
                  const float* __restrict__ A2, int lda2, int split,
                  const float* __restrict__ W,
                  const float* __restrict__ bias, int relu,
                  float* __restrict__ C, int N, int K)
{
    __shared__ float As[16][132];
    __shared__ float Bs[16][144];
    const int tid = threadIdx.x;
    const int tx = tid & 15, ty = tid >> 4;
    const int bm = blockIdx.y << 7, bn = blockIdx.x << 7;

    ull acc[8][4];
#pragma unroll
    for (int i = 0; i < 8; i++)
#pragma unroll
        for (int j = 0; j < 4; j++) acc[i][j] = 0ull;

    const int aq0 = tid, aq1 = tid + 256;
    const int ar0 = aq0 >> 2, ak0 = (aq0 & 3) << 2;
    const int ar1 = aq1 >> 2, ak1 = (aq1 & 3) << 2;
    const int bkk = tid >> 5, bcc = (tid & 31) << 2;

    float4 pa0, pa1, pb0, pb1;

    auto ldTiles = [&](int k0) {
        int kg0 = k0 + ak0;
        pa0 = (kg0 < split)
            ? *(const float4*)(A1 + (size_t)(bm + ar0) * lda1 + kg0)
            : *(const float4*)(A2 + (size_t)(bm + ar0) * lda2 + (kg0 - split));
        int kg1 = k0 + ak1;
        pa1 = (kg1 < split)
            ? *(const float4*)(A1 + (size_t)(bm + ar1) * lda1 + kg1)
            : *(const float4*)(A2 + (size_t)(bm + ar1) * lda2 + (kg1 - split));
        pb0 = *(const float4*)(W + (size_t)(k0 + bkk) * N + bn + bcc);
        pb1 = *(const float4*)(W + (size_t)(k0 + bkk + 8) * N + bn + bcc);
    };
    auto stTiles = [&]() {
        As[ak0 + 0][ar0] = pa0.x; As[ak0 + 1][ar0] = pa0.y;
        As[ak0 + 2][ar0] = pa0.z; As[ak0 + 3][ar0] = pa0.w;
        As[ak1 + 0][ar1] = pa1.x; As[ak1 + 1][ar1] = pa1.y;
        As[ak1 + 2][ar1] = pa1.z; As[ak1 + 3][ar1] = pa1.w;
        *(float4*)&Bs[bkk][swz(bcc)] = pb0;
        *(float4*)&Bs[bkk + 8][swz(bcc)] = pb1;
    };
    auto comp = [&]() {
#pragma unroll
        for (int kk = 0; kk < 16; kk++) {
            float4 a0 = *(const float4*)&As[kk][ty << 3];
            float4 a1 = *(const float4*)&As[kk][(ty << 3) + 4];
            ulonglong2 b01 = *(const ulonglong2*)&Bs[kk][swz(tx << 3)];
            ulonglong2 b23 = *(const ulonglong2*)&Bs[kk][swz((tx << 3) + 4)];
            float ar[8] = {a0.x, a0.y, a0.z, a0.w, a1.x, a1.y, a1.z, a1.w};
#pragma unroll
            for (int i = 0; i < 8; i++) {
                ull av = pk2(ar[i], ar[i]);
                fma2(acc[i][0], av, b01.x);
                fma2(acc[i][1], av, b01.y);
                fma2(acc[i][2], av, b23.x);
                fma2(acc[i][3], av, b23.y);
            }
        }
    };

    ldTiles(0);
    stTiles();
    __syncthreads();
    for (int k0 = 0; k0 < K; k0 += 16) {
        bool more = (k0 + 16) < K;
        if (more) ldTiles(k0 + 16);
        comp();
        __syncthreads();
        if (more) { stTiles(); __syncthreads(); }
    }

#pragma unroll
    for (int i = 0; i < 8; i++) {
        int row = bm + (ty << 3) + i;
        float* cp = C + (size_t)row * N + bn + (tx << 3);
#pragma unroll
        for (int j = 0; j < 4; j++) {
            float2 v = upk2(acc[i][j]);
            if (bias) {
                int col = bn + (tx << 3) + 2 * j;
                v.x += bias[col]; v.y += bias[col + 1];
            }
            if (relu) { v.x = fmaxf(v.x, 0.f); v.y = fmaxf(v.y, 0.f); }
            *(float2*)(cp + 2 * j) = v;
        }
    }
}

// ---------------- persistent LSTM scan (fp32) ----------------
#define SMEM_SCAN_FLOATS (18432 + 12800 + 192)

__device__ __forceinline__ void pre_xg(int t, int tid, int j0, float* xgv) {
    if (tid < 192) {
        int u = tid >> 5, b = tid & 31;
        const float* xp = g_xg + (size_t)(b * T_ + t) * G4 + j0 + u;
        xgv[0] = __ldcg(xp);
        xgv[1] = __ldcg(xp + H_);
        xgv[2] = __ldcg(xp + 2 * H_);
        xgv[3] = __ldcg(xp + 3 * H_);
    }
}

__global__ __launch_bounds__(512, 1)
void scan_kernel(const float* __restrict__ w_hh)
{
    extern __shared__ float sm[];
    float* w_s   = sm;                  // 18432 floats
    float* red_f = sm + 18432;          // 12800 floats (512 x 25)
    float* c_s   = red_f + 12800;       // 192 floats

    const int tid = threadIdx.x, lane = tid & 31, warp = tid >> 5;
    const int j0 = blockIdx.x * 6;

    for (int idx = tid; idx < 768 * 24; idx += 512) {
        int k = idx / 24, c = idx - k * 24;
        int q = c / 6, u = c - q * 6;
        w_s[idx] = w_hh[(size_t)k * G4 + q * H_ + j0 + u];
    }
    if (tid < 192) {
        c_s[tid] = 0.f;
        int u = tid >> 5, b = tid & 31;
        g_h[0][(j0 + u) * 32 + b] = 0.f;
    }
    __syncthreads();
    if (tid == 0) {
        __threadfence();
        asm volatile("st.release.gpu.u32 [%0],%1;"
                     :: "l"(&g_flag[blockIdx.x << 5]), "r"(1u) : "memory");
    }

    const unsigned* fp = &g_flag[((warp << 3) + (lane & 7)) << 5];

    float xga[4];
    pre_xg(0, tid, j0, xga);

    for (int t = 0; t < T_; t++) {
        const float* hcur = g_h[t & 1];
        float*       hnxt = g_h[(t + 1) & 1];
        const unsigned target = (unsigned)(t + 1);

        unsigned v;
        do {
            asm volatile("ld.acquire.gpu.u32 %0,[%1];" : "=r"(v) : "l"(fp) : "memory");
        } while (!__all_sync(0xffffffffu, v >= target));

        float xgb[4];
        pre_xg(t + 1 < T_ ? t + 1 : T_ - 1, tid, j0, xgb);

        const float* hp  = hcur + warp * 48 * 32 + lane;
        const float* wsp = w_s + warp * 48 * 24;

        float bufA[12], bufB[12];
#pragma unroll
        for (int i = 0; i < 12; i++) bufA[i] = __ldcg(hp + i * 32);
#pragma unroll
        for (int i = 0; i < 12; i++) bufB[i] = __ldcg(hp + (12 + i) * 32);

        ull acc[12];
#pragma unroll
        for (int j = 0; j < 12; j++) acc[j] = 0ull;

#pragma unroll
        for (int c = 0; c < 4; c++) {
            float* cur = (c & 1) ? bufB : bufA;
#pragma unroll
            for (int i = 0; i < 12; i++) {
                int k = c * 12 + i;
                ull hv = pk2(cur[i], cur[i]);
                const ulonglong2* wv = (const ulonglong2*)(wsp + k * 24);
                ulonglong2 w0 = wv[0], w1 = wv[1], w2 = wv[2];
                ulonglong2 w3 = wv[3], w4 = wv[4], w5 = wv[5];
                fma2(acc[0],  hv, w0.x); fma2(acc[1],  hv, w0.y);
                fma2(acc[2],  hv, w1.x); fma2(acc[3],  hv, w1.y);
                fma2(acc[4],  hv, w2.x); fma2(acc[5],  hv, w2.y);
                fma2(acc[6],  hv, w3.x); fma2(acc[7],  hv, w3.y);
                fma2(acc[8],  hv, w4.x); fma2(acc[9],  hv, w4.y);
                fma2(acc[10], hv, w5.x); fma2(acc[11], hv, w5.y);
            }
            if (c < 2) {
#pragma unroll
                for (int i = 0; i < 12; i++)
                    cur[i] = __ldcg(hp + ((c + 2) * 12 + i) * 32);
            }
        }

        {
            float* rp = red_f + tid * 25;
#pragma unroll
            for (int j = 0; j < 12; j++) {
                float2 v2 = upk2(acc[j]);
                rp[2 * j]     = v2.x;
                rp[2 * j + 1] = v2.y;
            }
        }
        __syncthreads();

        float hn = 0.f;
        if (tid < 192) {
            int u = tid >> 5, b = tid & 31;
            float pre[4];
#pragma unroll
            for (int q = 0; q < 4; q++) {
                int c = q * 6 + u;
                const float* rb = red_f + b * 25 + c;
                float s0 = xga[q], s1 = 0.f, s2 = 0.f, s3 = 0.f;
#pragma unroll
                for (int w = 0; w < 16; w += 4) {
                    s0 += rb[(w + 0) * 32 * 25];
                    s1 += rb[(w + 1) * 32 * 25];
                    s2 += rb[(w + 2) * 32 * 25];
                    s3 += rb[(w + 3) * 32 * 25];
                }
                pre[q] = (s0 + s1) + (s2 + s3);
            }
            float ig = sigf(pre[0]);
            float fg = sigf(pre[1]);
            float gg = tanh_(pre[2]);
            float og = sigf(pre[3]);
            float cn = fg * c_s[u * 32 + b] + ig * gg;
            c_s[u * 32 + b] = cn;
            hn = og * tanh_(cn);
            hnxt[(j0 + u) * 32 + b] = hn;
        }
        __syncthreads();
        if (tid == 0) {
            __threadfence();
            asm volatile("st.release.gpu.u32 [%0],%1;"
                         :: "l"(&g_flag[blockIdx.x << 5]), "r"((unsigned)(t + 2)) : "memory");
        }

        if (tid < 192) {
            int u = tid >> 5, b = tid & 31;
            g_hs[(size_t)(b * T_ + t) * H_ + j0 + u] = hn;
        }

        xga[0] = xgb[0]; xga[1] = xgb[1]; xga[2] = xgb[2]; xga[3] = xgb[3];
    }
}

// ---------------- host launcher ----------------
extern "C" void kernel_launch(void* const* d_in, const int* in_sizes, int n_in,
                              void* d_out, int out_size)
{
    const float* x      = (const float*)d_in[0];
    const float* mels   = (const float*)d_in[1];
    const float* w1     = (const float*)d_in[2];
    const float* b1     = (const float*)d_in[3];
    const float* w2     = (const float*)d_in[4];
    const float* b2     = (const float*)d_in[5];
    const float* w_ih   = (const float*)d_in[6];
    const float* w_hh   = (const float*)d_in[7];
    const float* b_ih   = (const float*)d_in[8];
    const float* b_hh   = (const float*)d_in[9];
    const float* w_proj = (const float*)d_in[10];
    float* out = (float*)d_out;

    float *p_m1, *p_m2, *p_hs;
    cudaGetSymbolAddress((void**)&p_m1, g_m1);
    cudaGetSymbolAddress((void**)&p_m2, g_m2);
    cudaGetSymbolAddress((void**)&p_hs, g_hs);

    cudaFuncSetAttribute(scan_kernel, cudaFuncAttributeMaxDynamicSharedMemorySize,
                         SMEM_SCAN_FLOATS * 4);
    cudaFuncSetAttribute(xg_wmma_kernel, cudaFuncAttributeMaxDynamicSharedMemorySize,
                         XS_TOTAL * 4);

    // fused bias + flag reset (must precede xg GEMM and scan)
    init_kernel<<<16, 256>>>(b_ih, b_hh);

    // PreNet layer 1: [65536,128] @ [128,256] + b1, relu
    sgemm_kernel<<<dim3(2, 512), 256>>>(mels, 128, mels, 128, 128,
                                        w1, b1, 1, p_m1, 256, 128);
    // PreNet layer 2: [65536,256] @ [256,256] + b2, relu
    sgemm_kernel<<<dim3(2, 512), 256>>>(p_m1, 256, p_m1, 256, 256,
                                        w2, b2, 1, p_m2, 256, 256);

    // xg = concat(x, m2) @ w_ih + bias  — tf32 mma.sync tensor cores
    xg_wmma_kernel<<<dim3(24, 512), 256, XS_TOTAL * 4>>>(x, p_m2, w_ih);

    // LSTM recurrence (persistent cooperative kernel, fp32)
    scan_kernel<<<128, 512, SMEM_SCAN_FLOATS * 4>>>(w_hh);

    // projection: [65536,768] @ [768,128]
    sgemm_kernel<<<dim3(1, 512), 256>>>(p_hs, 768, p_hs, 768, 768,
                                        w_proj, nullptr, 0, out, 128, 768);
}

// round 9
// speedup vs baseline: 1.4615x; 1.0214x over previous
#include <cuda_runtime.h>
#include <mma.h>
#include <cstdint>

using namespace nvcuda;

#define BT   65536
#define T_   2048
#define B_   32
#define H_   768
#define G4   3072

typedef unsigned long long ull;

// ---------------- scratch (static device memory; no allocs) ----------------
__device__ float g_m1[(size_t)BT * 256];
__device__ float g_m2[(size_t)BT * 256];
__device__ float g_xr[(size_t)BT * 512];    // x pre-rounded to tf32
__device__ float g_wr[(size_t)H_ * G4];     // w_ih pre-rounded to tf32
__device__ float g_xg[(size_t)BT * G4];     // [b*T+t][4H]
__device__ float g_hs[(size_t)BT * H_];     // [b*T+t][H]
__device__ float g_h[2][H_ * B_];           // double-buffered h, layout [j][b]
__device__ float g_bias[G4];
__device__ unsigned g_flag[128 * 32];       // per-block flags, 128B stride

// ---------------- helpers ----------------
__device__ __forceinline__ ull pk2(float lo, float hi) {
    ull r; asm("mov.b64 %0,{%1,%2};" : "=l"(r) : "f"(lo), "f"(hi)); return r;
}
__device__ __forceinline__ void fma2(ull& d, ull a, ull b) {
    asm("fma.rn.f32x2 %0,%1,%2,%0;" : "+l"(d) : "l"(a), "l"(b));
}
__device__ __forceinline__ float2 upk2(ull v) {
    float lo, hi; asm("mov.b64 {%0,%1},%2;" : "=f"(lo), "=f"(hi) : "l"(v));
    float2 r; r.x = lo; r.y = hi; return r;
}
__device__ __forceinline__ float sigf(float x) {
    return __fdividef(1.f, 1.f + __expf(-x));
}
__device__ __forceinline__ float tanh_(float x) {
    return 2.f * sigf(2.f * x) - 1.f;
}
__device__ __forceinline__ uint32_t smem_u32(const void* p) {
    uint32_t a;
    asm("{ .reg .u64 t; cvta.to.shared.u64 t, %1; cvt.u32.u64 %0, t; }" : "=r"(a) : "l"(p));
    return a;
}
__device__ __forceinline__ float rtf32(float f) {
    unsigned o; asm("cvt.rna.tf32.f32 %0, %1;" : "=r"(o) : "f"(f));
    return __uint_as_float(o);
}

// ---------------- init: fused bias + flag reset ----------------
__global__ void init_kernel(const float* __restrict__ bi, const float* __restrict__ bh) {
    int i = blockIdx.x * 256 + threadIdx.x;
    if (i < 128 * 32) g_flag[i] = 0u;
    if (i < G4) g_bias[i] = bi[i] + bh[i];
}

// ---------------- tf32 pre-rounding ----------------
__global__ void round_x_kernel(const float* __restrict__ x) {
    size_t i = ((size_t)blockIdx.x * 256 + threadIdx.x) * 4;
    float4 v = *(const float4*)(x + i);
    v.x = rtf32(v.x); v.y = rtf32(v.y); v.z = rtf32(v.z); v.w = rtf32(v.w);
    *(float4*)(g_xr + i) = v;
}
__global__ void round_w_kernel(const float* __restrict__ w) {
    size_t i = ((size_t)blockIdx.x * 256 + threadIdx.x) * 4;
    float4 v = *(const float4*)(w + i);
    v.x = rtf32(v.x); v.y = rtf32(v.y); v.z = rtf32(v.z); v.w = rtf32(v.w);
    *(float4*)(g_wr + i) = v;
}

// ---------------- tf32 WMMA GEMM for xg ----------------
// C[65536,3072] = concat(xr[.,512], m2[.,256]) @ Wr[768,3072] + bias
// Operands pre-rounded to tf32 -> no in-loop conversions.
#define XA_LD 36
#define XB_LD 132
#define XS_A  (128 * XA_LD)
#define XS_B  (32 * XB_LD)
#define XS_BIAS_OFF (2 * XS_A + 2 * XS_B)
#define XS_TOTAL (XS_BIAS_OFF + 16 * 128)   // floats

__global__ __launch_bounds__(256, 2)
void xg_wmma_kernel(const float* __restrict__ m2p)
{
    extern __shared__ float xsm[];
    float* As     = xsm;
    float* Bs     = xsm + 2 * XS_A;
    float* bias_s = xsm + XS_BIAS_OFF;

    const int tid = threadIdx.x;
    const int warp = tid >> 5;
    const int bm = blockIdx.y * 128, bn = blockIdx.x * 128;
    const int wm = (warp & 3) * 32;
    const int wn = (warp >> 2) * 64;

    for (int i = tid; i < 16 * 128; i += 256)
        bias_s[i] = g_bias[bn + (i & 127)];

    wmma::fragment<wmma::accumulator, 16, 16, 8, float> acc[2][4];
#pragma unroll
    for (int i = 0; i < 2; i++)
#pragma unroll
        for (int j = 0; j < 4; j++) wmma::fill_fragment(acc[i][j], 0.f);

    auto cp_tile = [&](int t, int buf) {
        const int kf = t * 32;
        float* ad = As + buf * XS_A;
#pragma unroll
        for (int i = 0; i < 4; i++) {
            int c = tid + 256 * i;
            int row = c >> 3, kc = (c & 7) * 4;
            int kg = kf + kc;
            const float* src = (kg < 512)
                ? (g_xr + (size_t)(bm + row) * 512 + kg)
                : (m2p  + (size_t)(bm + row) * 256 + (kg - 512));
            uint32_t d = smem_u32(ad + row * XA_LD + kc);
            asm volatile("cp.async.cg.shared.global [%0],[%1],16;" :: "r"(d), "l"(src));
        }
        float* bd = Bs + buf * XS_B;
#pragma unroll
        for (int i = 0; i < 4; i++) {
            int c = tid + 256 * i;
            int kr = c >> 5, nc = (c & 31) * 4;
            const float* src = g_wr + (size_t)(kf + kr) * G4 + bn + nc;
            uint32_t d = smem_u32(bd + kr * XB_LD + nc);
            asm volatile("cp.async.cg.shared.global [%0],[%1],16;" :: "r"(d), "l"(src));
        }
    };

    cp_tile(0, 0);
    asm volatile("cp.async.commit_group;" ::: "memory");

    for (int t = 0; t < 24; t++) {
        if (t + 1 < 24) {
            cp_tile(t + 1, (t + 1) & 1);
            asm volatile("cp.async.commit_group;" ::: "memory");
            asm volatile("cp.async.wait_group 1;" ::: "memory");
        } else {
            asm volatile("cp.async.wait_group 0;" ::: "memory");
        }
        __syncthreads();

        const float* At = As + (t & 1) * XS_A + wm * XA_LD;
        const float* Bt = Bs + (t & 1) * XS_B + wn;
#pragma unroll
        for (int ks = 0; ks < 4; ks++) {
            wmma::fragment<wmma::matrix_a, 16, 16, 8, wmma::precision::tf32,
                           wmma::row_major> af[2];
            wmma::fragment<wmma::matrix_b, 16, 16, 8, wmma::precision::tf32,
                           wmma::row_major> bf[4];
#pragma unroll
            for (int i = 0; i < 2; i++)
                wmma::load_matrix_sync(af[i], At + i * 16 * XA_LD + ks * 8, XA_LD);
#pragma unroll
            for (int j = 0; j < 4; j++)
                wmma::load_matrix_sync(bf[j], Bt + ks * 8 * XB_LD + j * 16, XB_LD);
#pragma unroll
            for (int i = 0; i < 2; i++)
#pragma unroll
                for (int j = 0; j < 4; j++)
                    wmma::mma_sync(acc[i][j], af[i], bf[j], acc[i][j]);
        }
        __syncthreads();
    }

    const int row0 = bm + wm, col0 = bn + wn;
#pragma unroll
    for (int i = 0; i < 2; i++)
#pragma unroll
        for (int j = 0; j < 4; j++) {
            wmma::fragment<wmma::accumulator, 16, 16, 8, float> bfr;
            wmma::load_matrix_sync(bfr, bias_s + wn + j * 16, 128, wmma::mem_row_major);
#pragma unroll
            for (int e = 0; e < bfr.num_elements; e++)
                acc[i][j].x[e] += bfr.x[e];
            wmma::store_matrix_sync(g_xg + (size_t)(row0 + i * 16) * G4 + col0 + j * 16,
                                    acc[i][j], G4, wmma::mem_row_major);
        }
}

// ---------------- generic fp32 SGEMM (prenet + proj) ----------------
__device__ __forceinline__ int swz(int c) { return c + ((c >> 5) << 2); }

__global__ __launch_bounds__(256, 2)
void sgemm_kernel(const float* __restrict__ A1, int lda1,
                  const float* __restrict__ A2, int lda2, int split,
                  const float* __restrict__ W,
                  const float* __restrict__ bias, int relu, int rnd,
                  float* __restrict__ C, int N, int K)
{
    __shared__ float As[16][132];
    __shared__ float Bs[16][144];
    const int tid = threadIdx.x;
    const int tx = tid & 15, ty = tid >> 4;
    const int bm = blockIdx.y << 7, bn = blockIdx.x << 7;

    ull acc[8][4];
#pragma unroll
    for (int i = 0; i < 8; i++)
#pragma unroll
        for (int j = 0; j < 4; j++) acc[i][j] = 0ull;

    const int aq0 = tid, aq1 = tid + 256;
    const int ar0 = aq0 >> 2, ak0 = (aq0 & 3) << 2;
    const int ar1 = aq1 >> 2, ak1 = (aq1 & 3) << 2;
    const int bkk = tid >> 5, bcc = (tid & 31) << 2;

    float4 pa0, pa1, pb0, pb1;

    auto ldTiles = [&](int k0) {
        int kg0 = k0 + ak0;
        pa0 = (kg0 < split)
            ? *(const float4*)(A1 + (size_t)(bm + ar0) * lda1 + kg0)
            : *(const float4*)(A2 + (size_t)(bm + ar0) * lda2 + (kg0 - split));
        int kg1 = k0 + ak1;
        pa1 = (kg1 < split)
            ? *(const float4*)(A1 + (size_t)(bm + ar1) * lda1 + kg1)
            : *(const float4*)(A2 + (size_t)(bm + ar1) * lda2 + (kg1 - split));
        pb0 = *(const float4*)(W + (size_t)(k0 + bkk) * N + bn + bcc);
        pb1 = *(const float4*)(W + (size_t)(k0 + bkk + 8) * N + bn + bcc);
    };
    auto stTiles = [&]() {
        As[ak0 + 0][ar0] = pa0.x; As[ak0 + 1][ar0] = pa0.y;
        As[ak0 + 2][ar0] = pa0.z; As[ak0 + 3][ar0] = pa0.w;
        As[ak1 + 0][ar1] = pa1.x; As[ak1 + 1][ar1] = pa1.y;
        As[ak1 + 2][ar1] = pa1.z; As[ak1 + 3][ar1] = pa1.w;
        *(float4*)&Bs[bkk][swz(bcc)] = pb0;
        *(float4*)&Bs[bkk + 8][swz(bcc)] = pb1;
    };
    auto comp = [&]() {
#pragma unroll
        for (int kk = 0; kk < 16; kk++) {
            float4 a0 = *(const float4*)&As[kk][ty << 3];
            float4 a1 = *(const float4*)&As[kk][(ty << 3) + 4];
            ulonglong2 b01 = *(const ulonglong2*)&Bs[kk][swz(tx << 3)];
            ulonglong2 b23 = *(const ulonglong2*)&Bs[kk][swz((tx << 3) + 4)];
            float ar[8] = {a0.x, a0.y, a0.z, a0.w, a1.x, a1.y, a1.z, a1.w};
#pragma unroll
            for (int i = 0; i < 8; i++) {
                ull av = pk2(ar[i], ar[i]);
                fma2(acc[i][0], av, b01.x);
                fma2(acc[i][1], av, b01.y);
                fma2(acc[i][2], av, b23.x);
                fma2(acc[i][3], av, b23.y);
            }
        }
    };

    ldTiles(0);
    stTiles();
    __syncthreads();
    for (int k0 = 0; k0 < K; k0 += 16) {
        bool more = (k0 + 16) < K;
        if (more) ldTiles(k0 + 16);
        comp();
        __syncthreads();
        if (more) { stTiles(); __syncthreads(); }
    }

#pragma unroll
    for (int i = 0; i < 8; i++) {
        int row = bm + (ty << 3) + i;
        float* cp = C + (size_t)row * N + bn + (tx << 3);
#pragma unroll
        for (int j = 0; j < 4; j++) {
            float2 v = upk2(acc[i][j]);
            if (bias) {
                int col = bn + (tx << 3) + 2 * j;
                v.x += bias[col]; v.y += bias[col + 1];
            }
            if (relu) { v.x = fmaxf(v.x, 0.f); v.y = fmaxf(v.y, 0.f); }
            if (rnd)  { v.x = rtf32(v.x); v.y = rtf32(v.y); }
            *(float2*)(cp + 2 * j) = v;
        }
    }
}

// ---------------- persistent LSTM scan (fp32) ----------------
// 128 blocks x 512 threads. Partials: red_f[warp][col*32+b] (RED_W stride),
// phase-1 sums spread across all 512 threads into red2[768].
#define RED_W 776
#define SMEM_SCAN_FLOATS (18432 + 16 * RED_W + 768 + 192)

__device__ __forceinline__ void pre_xg(int t, int tid, int j0, float* xgv) {
    if (tid < 192) {
        int u = tid >> 5, b = tid & 31;
        const float* xp = g_xg + (size_t)(b * T_ + t) * G4 + j0 + u;
        xgv[0] = __ldcg(xp);
        xgv[1] = __ldcg(xp + H_);
        xgv[2] = __ldcg(xp + 2 * H_);
        xgv[3] = __ldcg(xp + 3 * H_);
    }
}

__global__ __launch_bounds__(512, 1)
void scan_kernel(const float* __restrict__ w_hh)
{
    extern __shared__ float sm[];
    float* w_s   = sm;                       // 18432
    float* red_f = sm + 18432;               // 16 * RED_W
    float* red2  = red_f + 16 * RED_W;       // 768
    float* c_s   = red2 + 768;               // 192

    const int tid = threadIdx.x, lane = tid & 31, warp = tid >> 5;
    const int j0 = blockIdx.x * 6;

    for (int idx = tid; idx < 768 * 24; idx += 512) {
        int k = idx / 24, c = idx - k * 24;
        int q = c / 6, u = c - q * 6;
        w_s[idx] = w_hh[(size_t)k * G4 + q * H_ + j0 + u];
    }
    if (tid < 192) {
        c_s[tid] = 0.f;
        int u = tid >> 5, b = tid & 31;
        g_h[0][(j0 + u) * 32 + b] = 0.f;
    }
    __syncthreads();
    if (tid == 0) {
        __threadfence();
        asm volatile("st.release.gpu.u32 [%0],%1;"
                     :: "l"(&g_flag[blockIdx.x << 5]), "r"(1u) : "memory");
    }

    const unsigned* fp = &g_flag[((warp << 3) + (lane & 7)) << 5];

    float xga[4];
    pre_xg(0, tid, j0, xga);

    for (int t = 0; t < T_; t++) {
        const float* hcur = g_h[t & 1];
        float*       hnxt = g_h[(t + 1) & 1];
        const unsigned target = (unsigned)(t + 1);

        unsigned v;
        do {
            asm volatile("ld.acquire.gpu.u32 %0,[%1];" : "=r"(v) : "l"(fp) : "memory");
        } while (!__all_sync(0xffffffffu, v >= target));

        float xgb[4];
        pre_xg(t + 1 < T_ ? t + 1 : T_ - 1, tid, j0, xgb);

        const float* hp  = hcur + warp * 48 * 32 + lane;
        const float* wsp = w_s + warp * 48 * 24;

        float bufA[12], bufB[12];
#pragma unroll
        for (int i = 0; i < 12; i++) bufA[i] = __ldcg(hp + i * 32);
#pragma unroll
        for (int i = 0; i < 12; i++) bufB[i] = __ldcg(hp + (12 + i) * 32);

        ull acc[12];
#pragma unroll
        for (int j = 0; j < 12; j++) acc[j] = 0ull;

#pragma unroll
        for (int c = 0; c < 4; c++) {
            float* cur = (c & 1) ? bufB : bufA;
#pragma unroll
            for (int i = 0; i < 12; i++) {
                int k = c * 12 + i;
                ull hv = pk2(cur[i], cur[i]);
                const ulonglong2* wv = (const ulonglong2*)(wsp + k * 24);
                ulonglong2 w0 = wv[0], w1 = wv[1], w2 = wv[2];
                ulonglong2 w3 = wv[3], w4 = wv[4], w5 = wv[5];
                fma2(acc[0],  hv, w0.x); fma2(acc[1],  hv, w0.y);
                fma2(acc[2],  hv, w1.x); fma2(acc[3],  hv, w1.y);
                fma2(acc[4],  hv, w2.x); fma2(acc[5],  hv, w2.y);
                fma2(acc[6],  hv, w3.x); fma2(acc[7],  hv, w3.y);
                fma2(acc[8],  hv, w4.x); fma2(acc[9],  hv, w4.y);
                fma2(acc[10], hv, w5.x); fma2(acc[11], hv, w5.y);
            }
            if (c < 2) {
#pragma unroll
                for (int i = 0; i < 12; i++)
                    cur[i] = __ldcg(hp + ((c + 2) * 12 + i) * 32);
            }
        }

        // partials: warp base RED_W; cols (2j,2j+1) for lane b at float idx j*64+2b
        {
            float* rp = red_f + warp * RED_W + 2 * lane;
#pragma unroll
            for (int j = 0; j < 12; j++) {
                float2 v2 = upk2(acc[j]);
                *(float2*)(rp + j * 64) = v2;
            }
        }
        __syncthreads();

        // phase 1: all 512 threads sum the 16 warp partials for 768 (col,b) slots
        for (int s = tid; s < 768; s += 512) {
            float a0 = 0.f, a1 = 0.f, a2 = 0.f, a3 = 0.f;
#pragma unroll
            for (int w = 0; w < 16; w += 4) {
                a0 += red_f[(w + 0) * RED_W + s];
                a1 += red_f[(w + 1) * RED_W + s];
                a2 += red_f[(w + 2) * RED_W + s];
                a3 += red_f[(w + 3) * RED_W + s];
            }
            red2[s] = (a0 + a1) + (a2 + a3);
        }
        __syncthreads();

        // phase 2: gates
        float hn = 0.f;
        if (tid < 192) {
            int u = tid >> 5, b = tid & 31;
            float pre[4];
#pragma unroll
            for (int q = 0; q < 4; q++) {
                int c = q * 6 + u;
                pre[q] = xga[q] + red2[(c >> 1) * 64 + 2 * b + (c & 1)];
            }
            float ig = sigf(pre[0]);
            float fg = sigf(pre[1]);
            float gg = tanh_(pre[2]);
            float og = sigf(pre[3]);
            float cn = fg * c_s[u * 32 + b] + ig * gg;
            c_s[u * 32 + b] = cn;
            hn = og * tanh_(cn);
            hnxt[(j0 + u) * 32 + b] = hn;
        }
        __syncthreads();
        if (tid == 0) {
            __threadfence();
            asm volatile("st.release.gpu.u32 [%0],%1;"
                         :: "l"(&g_flag[blockIdx.x << 5]), "r"((unsigned)(t + 2)) : "memory");
        }

        if (tid < 192) {
            int u = tid >> 5, b = tid & 31;
            g_hs[(size_t)(b * T_ + t) * H_ + j0 + u] = hn;
        }

        xga[0] = xgb[0]; xga[1] = xgb[1]; xga[2] = xgb[2]; xga[3] = xgb[3];
    }
}

// ---------------- host launcher ----------------
extern "C" void kernel_launch(void* const* d_in, const int* in_sizes, int n_in,
                              void* d_out, int out_size)
{
    const float* x      = (const float*)d_in[0];
    const float* mels   = (const float*)d_in[1];
    const float* w1     = (const float*)d_in[2];
    const float* b1     = (const float*)d_in[3];
    const float* w2     = (const float*)d_in[4];
    const float* b2     = (const float*)d_in[5];
    const float* w_ih   = (const float*)d_in[6];
    const float* w_hh   = (const float*)d_in[7];
    const float* b_ih   = (const float*)d_in[8];
    const float* b_hh   = (const float*)d_in[9];
    const float* w_proj = (const float*)d_in[10];
    float* out = (float*)d_out;

    float *p_m1, *p_m2, *p_hs;
    cudaGetSymbolAddress((void**)&p_m1, g_m1);
    cudaGetSymbolAddress((void**)&p_m2, g_m2);
    cudaGetSymbolAddress((void**)&p_hs, g_hs);

    cudaFuncSetAttribute(scan_kernel, cudaFuncAttributeMaxDynamicSharedMemorySize,
                         SMEM_SCAN_FLOATS * 4);
    cudaFuncSetAttribute(xg_wmma_kernel, cudaFuncAttributeMaxDynamicSharedMemorySize,
                         XS_TOTAL * 4);

    // init + tf32 pre-rounding
    init_kernel<<<16, 256>>>(b_ih, b_hh);
    round_x_kernel<<<BT * 512 / 1024, 256>>>(x);
    round_w_kernel<<<H_ * G4 / 1024, 256>>>(w_ih);

    // PreNet layer 1: [65536,128] @ [128,256] + b1, relu
    sgemm_kernel<<<dim3(2, 512), 256>>>(mels, 128, mels, 128, 128,
                                        w1, b1, 1, 0, p_m1, 256, 128);
    // PreNet layer 2: + b2, relu, output rounded to tf32 (feeds xg tensor GEMM)
    sgemm_kernel<<<dim3(2, 512), 256>>>(p_m1, 256, p_m1, 256, 256,
                                        w2, b2, 1, 1, p_m2, 256, 256);

    // xg = concat(xr, m2) @ wr + bias  — tf32 mma.sync, pre-rounded operands
    xg_wmma_kernel<<<dim3(24, 512), 256, XS_TOTAL * 4>>>(p_m2);

    // LSTM recurrence (persistent cooperative kernel, fp32)
    scan_kernel<<<128, 512, SMEM_SCAN_FLOATS * 4>>>(w_hh);

    // projection: [65536,768] @ [768,128]
    sgemm_kernel<<<dim3(1, 512), 256>>>(p_hs, 768, p_hs, 768, 768,
                                        w_proj, nullptr, 0, 0, out, 128, 768);
}